// round 13
// baseline (speedup 1.0000x reference)
#include <cuda_runtime.h>
#include <math.h>

#define N_NODES_MAX 50000
#define E_MAX 800000
#define N_GRAPHS 512
#define HID 128

typedef unsigned long long ull;

// ------------- scratch (zero at load; zero-invariants maintained) ----------
__device__ float g_h[(size_t)N_NODES_MAX * HID];    // xW1
__device__ float g_a[(size_t)N_NODES_MAX * HID];    // act1' (pre-scaled)
__device__ int   g_degi[N_NODES_MAX];               // INVARIANT: zero between calls
__device__ int   g_off[N_NODES_MAX + 1];
__device__ float g_dinv[N_NODES_MAX];               // 1/sqrt(deg+1)
__device__ int   g_rank[E_MAX];                     // per-edge rank within dst
__device__ int   g_csr[E_MAX];                      // src ids grouped by dst
__device__ int   g_bsum[64];                        // zeroed by rank_k block 0
__device__ float g_sums[N_GRAPHS * HID];            // INVARIANT: zero between calls
__device__ float g_cnt[N_GRAPHS];                   // INVARIANT: zero between calls
__device__ int   g_is64;

// ---------------- packed f32x2 helpers ----------------
__device__ __forceinline__ ull pk2(float a, float b) {
    ull r;
    asm("mov.b64 %0, {%1, %2};" : "=l"(r) : "f"(a), "f"(b));
    return r;
}
__device__ __forceinline__ float2 upk2(ull v) {
    float2 f;
    asm("mov.b64 {%0, %1}, %2;" : "=f"(f.x), "=f"(f.y) : "l"(v));
    return f;
}
__device__ __forceinline__ void ffma2(ull& d, ull a, ull b) {
    asm("fma.rn.f32x2 %0, %1, %2, %3;" : "=l"(d) : "l"(a), "l"(b), "l"(d));
}
__device__ __forceinline__ int load_idx(const void* p, long i, int is64) {
    if (is64) return (int)((const long long*)p)[i];
    return ((const int*)p)[i];
}
__device__ __forceinline__ void red_add_v4(float* addr, float4 v) {
    size_t ga = __cvta_generic_to_global(addr);
    asm volatile("red.global.add.v4.f32 [%0], {%1, %2, %3, %4};"
                 :: "l"(ga), "f"(v.x), "f"(v.y), "f"(v.z), "f"(v.w) : "memory");
}

// ------- rank pass: degree histogram + per-edge rank + dtype detect ---------
__global__ void rank_k(const void* __restrict__ ei, int E) {
    __shared__ int s64;
    if (threadIdx.x == 0) {
        const ull* e = (const ull*)ei;
        int f = 1;
#pragma unroll
        for (int i = 0; i < 16; i++)
            if (e[i] >> 32) f = 0;
        s64 = f;
        if (blockIdx.x == 0) g_is64 = f;
    }
    if (blockIdx.x == 0 && threadIdx.x < 64) g_bsum[threadIdx.x] = 0;
    __syncthreads();
    int is64 = s64;
    long base = ((long)blockIdx.x * blockDim.x + threadIdx.x) * 8;
#pragma unroll
    for (int j = 0; j < 8; j++) {
        long e = base + j;
        if (e < E) {
            int d = load_idx(ei, (long)E + e, is64);
            g_rank[e] = atomicAdd(&g_degi[d], 1);
        }
    }
}

// ------- single-pass scan with decoupled lookback; restores g_degi=0 --------
__global__ void scan_k(int n, int nblk) {
    cudaGridDependencySynchronize();
    __shared__ int wsum[32];
    __shared__ int s_carry;
    const int tid = threadIdx.x, lane = tid & 31, w = tid >> 5;
    const int b = blockIdx.x;
    int i = b * 1024 + tid;
    int v = (i < n) ? g_degi[i] : 0;
    if (i < n) g_degi[i] = 0;          // restore zero-invariant
    int x = v;
#pragma unroll
    for (int o = 1; o < 32; o <<= 1) {
        int y = __shfl_up_sync(~0u, x, o);
        if (lane >= o) x += y;
    }
    if (lane == 31) wsum[w] = x;
    __syncthreads();
    if (w == 0) {
        int s = wsum[lane];
#pragma unroll
        for (int o = 1; o < 32; o <<= 1) {
            int y = __shfl_up_sync(~0u, s, o);
            if (lane >= o) s += y;
        }
        wsum[lane] = s;
    }
    __syncthreads();
    int pre = (w > 0) ? wsum[w - 1] : 0;
    int incl = pre + x;
    int btotal = wsum[31];
    if (tid == 0) atomicExch(&g_bsum[b], btotal + 1);
    if (w == 0) {
        int sum = 0;
        for (int base = 0; base < b; base += 32) {
            int idx = base + lane;
            int val = 0;
            if (idx < b) {
                do { val = atomicAdd(&g_bsum[idx], 0); } while (val == 0);
                sum += val - 1;
            }
        }
#pragma unroll
        for (int o = 16; o; o >>= 1)
            sum += __shfl_down_sync(~0u, sum, o);
        if (lane == 0) s_carry = sum;
    }
    __syncthreads();
    int bpre = s_carry;
    if (i < n) {
        g_off[i] = bpre + incl - v;
        g_dinv[i] = rsqrtf((float)v + 1.0f);
    }
    if (b == nblk - 1 && tid == 1023) g_off[n] = bpre + incl;
}

// ---------- CSR fill: NO atomics. PDL: pre-load edge list before gridsync ---
__global__ void fill2_k(const void* __restrict__ ei, int E) {
    __shared__ int s64;
    if (threadIdx.x == 0) {      // local dtype re-detect (ei is a stable input)
        const ull* e = (const ull*)ei;
        int f = 1;
#pragma unroll
        for (int i = 0; i < 16; i++)
            if (e[i] >> 32) f = 0;
        s64 = f;
    }
    __syncthreads();
    int is64 = s64;
    long base = ((long)blockIdx.x * blockDim.x + threadIdx.x) * 8;
    int s[8], d[8];
#pragma unroll
    for (int j = 0; j < 8; j++) {
        long e = base + j;
        if (e < E) {
            s[j] = load_idx(ei, e, is64);
            d[j] = load_idx(ei, (long)E + e, is64);
        } else d[j] = -1;
    }
    cudaGridDependencySynchronize();
#pragma unroll
    for (int j = 0; j < 8; j++) {
        long e = base + j;
        if (d[j] >= 0) g_csr[g_off[d[j]] + g_rank[e]] = s[j];
    }
}

// ------ layer-1 gather: warp per dst node, weighted, emits act1' -------------
// out = dinv_d * relu( dinv_d*(sum_s dinv_s*v_s + dinv_d*v_d) + bias )
__global__ void gather128_k(const float* __restrict__ feat,
                            const float* __restrict__ bias,
                            float* __restrict__ out, int n) {
    int node = blockIdx.x * (blockDim.x >> 5) + (threadIdx.x >> 5);
    if (node >= n) return;
    const int lane = threadIdx.x & 31;
    int p = g_off[node], pend = g_off[node + 1];
    const float4* f4 = (const float4*)feat;
    float dd = g_dinv[node];

    float4 acc = make_float4(0.f, 0.f, 0.f, 0.f);
    for (; p + 8 <= pend; p += 8) {
        int s[8]; float4 v[8]; float nn[8];
#pragma unroll
        for (int j = 0; j < 8; j++) s[j] = __ldg(&g_csr[p + j]);
#pragma unroll
        for (int j = 0; j < 8; j++) v[j] = __ldg(&f4[(long)s[j] * 32 + lane]);
#pragma unroll
        for (int j = 0; j < 8; j++) nn[j] = __ldg(&g_dinv[s[j]]);
#pragma unroll
        for (int j = 0; j < 8; j++) {
            acc.x = fmaf(v[j].x, nn[j], acc.x);
            acc.y = fmaf(v[j].y, nn[j], acc.y);
            acc.z = fmaf(v[j].z, nn[j], acc.z);
            acc.w = fmaf(v[j].w, nn[j], acc.w);
        }
    }
    if (p + 4 <= pend) {
        int s[4]; float4 v[4]; float nn[4];
#pragma unroll
        for (int j = 0; j < 4; j++) s[j] = __ldg(&g_csr[p + j]);
#pragma unroll
        for (int j = 0; j < 4; j++) v[j] = __ldg(&f4[(long)s[j] * 32 + lane]);
#pragma unroll
        for (int j = 0; j < 4; j++) nn[j] = __ldg(&g_dinv[s[j]]);
#pragma unroll
        for (int j = 0; j < 4; j++) {
            acc.x = fmaf(v[j].x, nn[j], acc.x);
            acc.y = fmaf(v[j].y, nn[j], acc.y);
            acc.z = fmaf(v[j].z, nn[j], acc.z);
            acc.w = fmaf(v[j].w, nn[j], acc.w);
        }
        p += 4;
    }
    for (; p < pend; p++) {
        int s0 = __ldg(&g_csr[p]);
        float n0 = __ldg(&g_dinv[s0]);
        float4 v0 = __ldg(&f4[(long)s0 * 32 + lane]);
        acc.x = fmaf(v0.x, n0, acc.x); acc.y = fmaf(v0.y, n0, acc.y);
        acc.z = fmaf(v0.z, n0, acc.z); acc.w = fmaf(v0.w, n0, acc.w);
    }
    float4 sv = __ldg(&f4[(long)node * 32 + lane]);
    acc.x = fmaf(sv.x, dd, acc.x); acc.y = fmaf(sv.y, dd, acc.y);
    acc.z = fmaf(sv.z, dd, acc.z); acc.w = fmaf(sv.w, dd, acc.w);
    float4 bb = __ldg(&((const float4*)bias)[lane]);
    acc.x = dd * fmaxf(fmaf(acc.x, dd, bb.x), 0.f);
    acc.y = dd * fmaxf(fmaf(acc.y, dd, bb.y), 0.f);
    acc.z = dd * fmaxf(fmaf(acc.z, dd, bb.z), 0.f);
    acc.w = dd * fmaxf(fmaf(acc.w, dd, bb.w), 0.f);
    ((float4*)out)[(long)node * 32 + lane] = acc;
}

// ------- FUSED layer 2: gather(act1') -> gemm(W2) -> bias+relu -> pool ------
// Block = 256 thr, 64 nodes. Warp w gathers nodes [rbase+8w, rbase+8w+8) fully
// into registers (acc[8] float4 = each lane holds cols [4*lane,4*lane+4)).
// Then k-tiled gemm stages the register rows into a 16KB smem X slice per kt.
__global__ void fgg_k(const float* __restrict__ feat, const float* __restrict__ W,
                      const float* __restrict__ bias,
                      const void* __restrict__ batch, int n) {
    __shared__ ulonglong2 Ws2[32 * 32];   // 16 KB, restaged per kt
    __shared__ ull Xs2[64 * 32];          // 16 KB, restaged per kt
    const int tid  = threadIdx.x;
    const int lane = tid & 31;
    const int warp = tid >> 5;
    const int rbase = blockIdx.x * 64;
    const int kgrp = lane >> 3;           // which kt this lane's cols belong to
    const int j8   = lane & 7;            // position within that k-group

    // pre-sync: stage W tile kt=0 (W is a stable input)
#pragma unroll
    for (int q = 0; q < 4; q++) {
        int f = tid + q * 256;
        float4 w = __ldg(&((const float4*)W)[f]);
        Ws2[f] = make_ulonglong2(pk2(w.x, w.y), pk2(w.z, w.w));
    }
    cudaGridDependencySynchronize();

    // ---- phase A: gather 8 nodes per warp into registers ----
    const float4* f4 = (const float4*)feat;
    float4 acc[8];
#pragma unroll
    for (int r = 0; r < 8; r++) {
        acc[r] = make_float4(0.f, 0.f, 0.f, 0.f);
        int node = rbase + warp * 8 + r;
        if (node >= n) continue;
        int p = g_off[node], pend = g_off[node + 1];
        float4 a = make_float4(0.f, 0.f, 0.f, 0.f);
#pragma unroll 1
        for (; p + 4 <= pend; p += 4) {
            int s[4]; float4 v[4];
#pragma unroll
            for (int j = 0; j < 4; j++) s[j] = __ldg(&g_csr[p + j]);
#pragma unroll
            for (int j = 0; j < 4; j++) v[j] = __ldg(&f4[(long)s[j] * 32 + lane]);
#pragma unroll
            for (int j = 0; j < 4; j++) {
                a.x += v[j].x; a.y += v[j].y; a.z += v[j].z; a.w += v[j].w;
            }
        }
#pragma unroll 1
        for (; p < pend; p++) {
            int s0 = __ldg(&g_csr[p]);
            float4 v0 = __ldg(&f4[(long)s0 * 32 + lane]);
            a.x += v0.x; a.y += v0.y; a.z += v0.z; a.w += v0.w;
        }
        float4 sv = __ldg(&f4[(long)node * 32 + lane]);
        float dd = g_dinv[node];
        acc[r].x = dd * (a.x + sv.x);
        acc[r].y = dd * (a.y + sv.y);
        acc[r].z = dd * (a.z + sv.z);
        acc[r].w = dd * (a.w + sv.w);
    }

    // ---- phase B: k-tiled gemm from register rows ----
    ull acc2[8][2];
#pragma unroll
    for (int r = 0; r < 8; r++) { acc2[r][0] = 0ull; acc2[r][1] = 0ull; }

    for (int kt = 0; kt < 4; kt++) {
        if (kt > 0) {
            __syncthreads();   // previous tile fully consumed
#pragma unroll
            for (int q = 0; q < 4; q++) {
                int f = tid + q * 256;
                float4 w = __ldg(&((const float4*)W)[kt * 1024 + f]);
                Ws2[f] = make_ulonglong2(pk2(w.x, w.y), pk2(w.z, w.w));
            }
        }
        // write this warp's rows' kt-slice (lanes whose cols fall in tile kt)
        if (kgrp == kt) {
#pragma unroll
            for (int r = 0; r < 8; r++) {
                int bb = (warp * 8 + r) * 32 + j8 * 4;
                Xs2[bb + 0] = pk2(acc[r].x, acc[r].x);
                Xs2[bb + 1] = pk2(acc[r].y, acc[r].y);
                Xs2[bb + 2] = pk2(acc[r].z, acc[r].z);
                Xs2[bb + 3] = pk2(acc[r].w, acc[r].w);
            }
        }
        __syncthreads();
#pragma unroll
        for (int k = 0; k < 32; k++) {
            ulonglong2 w2 = Ws2[k * 32 + lane];
#pragma unroll
            for (int r = 0; r < 8; r++) {
                ull xx = Xs2[(warp * 8 + r) * 32 + k];
                ffma2(acc2[r][0], xx, w2.x);
                ffma2(acc2[r][1], xx, w2.y);
            }
        }
    }

    // ---- epilogue: bias + relu + pool-reduce ----
    float4 bb = __ldg(&((const float4*)bias)[lane]);
    int is64 = g_is64;
#pragma unroll
    for (int r = 0; r < 8; r++) {
        int row = rbase + warp * 8 + r;
        if (row < n) {
            float2 a = upk2(acc2[r][0]);
            float2 b = upk2(acc2[r][1]);
            float4 o;
            o.x = fmaxf(a.x + bb.x, 0.f);
            o.y = fmaxf(a.y + bb.y, 0.f);
            o.z = fmaxf(b.x + bb.z, 0.f);
            o.w = fmaxf(b.y + bb.w, 0.f);
            int g = load_idx(batch, row, is64);
            red_add_v4(g_sums + (long)g * HID + lane * 4, o);
            if (lane == 0) atomicAdd(&g_cnt[g], 1.0f);
        }
    }
}

// ------- dense transform (layer 1 fork): h1 = X @ W1, plain store -----------
__global__ void gemm96_k(const float* __restrict__ X, const float* __restrict__ W,
                         float* __restrict__ out, int n) {
    __shared__ ulonglong2 Ws2[32 * 32];
    __shared__ ull Xs2[64 * 32];
    const int tid  = threadIdx.x;
    const int lane = tid & 31;
    const int warp = tid >> 5;
    const int rbase = blockIdx.x * 64;

    ull acc[8][2];
#pragma unroll
    for (int r = 0; r < 8; r++) { acc[r][0] = 0ull; acc[r][1] = 0ull; }

    for (int kt = 0; kt < 3; kt++) {
#pragma unroll
        for (int j = 0; j < 4; j++) {
            int f = tid + j * 256;
            float4 w = __ldg(&((const float4*)W)[kt * 1024 + f]);
            Ws2[f] = make_ulonglong2(pk2(w.x, w.y), pk2(w.z, w.w));
        }
#pragma unroll
        for (int j = 0; j < 2; j++) {
            int f = tid + j * 256;
            int row = f >> 3;
            int kq = f & 7;
            int gr = rbase + row;
            float4 v = make_float4(0.f, 0.f, 0.f, 0.f);
            if (gr < n)
                v = *(const float4*)(X + (long)gr * 96 + kt * 32 + kq * 4);
            int bb = row * 32 + kq * 4;
            Xs2[bb + 0] = pk2(v.x, v.x);
            Xs2[bb + 1] = pk2(v.y, v.y);
            Xs2[bb + 2] = pk2(v.z, v.z);
            Xs2[bb + 3] = pk2(v.w, v.w);
        }
        __syncthreads();
#pragma unroll
        for (int k = 0; k < 32; k++) {
            ulonglong2 w2 = Ws2[k * 32 + lane];
#pragma unroll
            for (int r = 0; r < 8; r++) {
                ull xx = Xs2[(warp * 8 + r) * 32 + k];
                ffma2(acc[r][0], xx, w2.x);
                ffma2(acc[r][1], xx, w2.y);
            }
        }
        __syncthreads();
    }
#pragma unroll
    for (int r = 0; r < 8; r++) {
        int row = rbase + warp * 8 + r;
        if (row < n) {
            float2 a = upk2(acc[r][0]);
            float2 b = upk2(acc[r][1]);
            *(float4*)(out + (long)row * HID + lane * 4) =
                make_float4(a.x, a.y, b.x, b.y);
        }
    }
}

// ------- mean + final linear (+ zero-restore g_sums/g_cnt); PDL-synced ------
__global__ void final_k(const float* __restrict__ Wlin, const float* __restrict__ blin,
                        float* __restrict__ out) {
    int g = blockIdx.x;
    int t = threadIdx.x;  // 128
    float w0 = Wlin[2 * t], w1 = Wlin[2 * t + 1];
    cudaGridDependencySynchronize();
    float c = fmaxf(g_cnt[g], 1.0f);
    float s = g_sums[g * HID + t] / c;
    g_sums[g * HID + t] = 0.f;
    if (t == 0) g_cnt[g] = 0.f;
    float p0 = s * w0;
    float p1 = s * w1;
#pragma unroll
    for (int off = 16; off; off >>= 1) {
        p0 += __shfl_down_sync(0xffffffffu, p0, off);
        p1 += __shfl_down_sync(0xffffffffu, p1, off);
    }
    __shared__ float s0[4], s1[4];
    int w = t >> 5;
    if ((t & 31) == 0) { s0[w] = p0; s1[w] = p1; }
    __syncthreads();
    if (t == 0) {
        out[g * 2 + 0] = s0[0] + s0[1] + s0[2] + s0[3] + blin[0];
        out[g * 2 + 1] = s1[0] + s1[1] + s1[2] + s1[3] + blin[1];
    }
}

// ---------------- PDL launch helper ----------------
template <typename F, typename... Args>
static void launch_pdl(F f, dim3 grid, dim3 block, cudaStream_t st, Args... args) {
    cudaLaunchConfig_t cfg = {};
    cfg.gridDim = grid;
    cfg.blockDim = block;
    cfg.dynamicSmemBytes = 0;
    cfg.stream = st;
    cudaLaunchAttribute attr[1];
    attr[0].id = cudaLaunchAttributeProgrammaticStreamSerialization;
    attr[0].val.programmaticStreamSerializationAllowed = 1;
    cfg.attrs = attr;
    cfg.numAttrs = 1;
    cudaLaunchKernelEx(&cfg, f, args...);
}

// ---------------- launcher ----------------
extern "C" void kernel_launch(void* const* d_in, const int* in_sizes, int n_in,
                              void* d_out, int out_size) {
    (void)out_size;
    const float* x     = (const float*)d_in[0];
    const void*  ei    = d_in[1];
    const void*  batch = d_in[2];
    int base = (n_in >= 10) ? 4 : 3;
    const float* W1   = (const float*)d_in[base + 0];
    const float* b1   = (const float*)d_in[base + 1];
    const float* W2   = (const float*)d_in[base + 2];
    const float* b2   = (const float*)d_in[base + 3];
    const float* Wlin = (const float*)d_in[base + 4];
    const float* blin = (const float*)d_in[base + 5];

    const int N = in_sizes[0] / 96;
    const int E = in_sizes[1] / 2;
    const int NBLK = (N + 1023) >> 10;  // <= 49
    float* out = (float*)d_out;

    static cudaStream_t s1 = 0;
    static cudaEvent_t evF, evJ;
    if (!s1) {
        cudaStreamCreateWithFlags(&s1, cudaStreamNonBlocking);
        cudaEventCreateWithFlags(&evF, cudaEventDisableTiming);
        cudaEventCreateWithFlags(&evJ, cudaEventDisableTiming);
    }

    void *p_a, *p_h;
    cudaGetSymbolAddress(&p_a, g_a);
    cudaGetSymbolAddress(&p_h, g_h);

    // fork: h1 = x @ W1 on s1 (independent of graph prep)
    cudaEventRecord(evF, 0);
    cudaStreamWaitEvent(s1, evF, 0);
    gemm96_k<<<(N + 63) / 64, 256, 0, s1>>>(x, W1, (float*)p_h, N);
    cudaEventRecord(evJ, s1);

    // prep chain on stream 0 (no memsets; PDL-overlapped boundaries)
    rank_k<<<(E + 2047) / 2048, 256>>>(ei, E);
    launch_pdl(scan_k, dim3(NBLK), dim3(1024), (cudaStream_t)0, N, NBLK);
    launch_pdl(fill2_k, dim3((E + 2047) / 2048), dim3(256), (cudaStream_t)0,
               ei, E);

    // join, then layer-1 aggregate (normal launch: cross-stream dependency)
    cudaStreamWaitEvent(0, evJ, 0);
    gather128_k<<<(N + 7) / 8, 256>>>((const float*)p_h, b1, (float*)p_a, N);

    // layer 2 fused: gather(act1') + gemm(W2) + bias + relu + pool
    launch_pdl(fgg_k, dim3((N + 63) / 64), dim3(256), (cudaStream_t)0,
               (const float*)p_a, W2, b2, (const void*)batch, N);

    launch_pdl(final_k, dim3(N_GRAPHS), dim3(HID), (cudaStream_t)0,
               Wlin, blin, out);
}

// round 14
// speedup vs baseline: 1.1111x; 1.1111x over previous
#include <cuda_runtime.h>
#include <math.h>

#define N_NODES_MAX 50000
#define E_MAX 800000
#define N_GRAPHS 512
#define HID 128

typedef unsigned long long ull;

// ------------- scratch (zero at load; zero-invariants maintained) ----------
__device__ float g_h[(size_t)N_NODES_MAX * HID];    // xW1 / gather2 out
__device__ float g_a[(size_t)N_NODES_MAX * HID];    // act1' (pre-scaled)
__device__ int   g_degi[N_NODES_MAX];               // INVARIANT: zero between calls
__device__ int   g_off[N_NODES_MAX + 1];
__device__ float g_dinv[N_NODES_MAX];               // 1/sqrt(deg+1)
__device__ int   g_rank[E_MAX];                     // per-edge rank within dst
__device__ int   g_csr[E_MAX];                      // src ids grouped by dst
__device__ int   g_bsum[64];                        // zeroed by rank_k block 0
__device__ float g_sums[N_GRAPHS * HID];            // INVARIANT: zero between calls
__device__ float g_cnt[N_GRAPHS];                   // INVARIANT: zero between calls
__device__ int   g_is64;

// ---------------- packed f32x2 helpers ----------------
__device__ __forceinline__ ull pk2(float a, float b) {
    ull r;
    asm("mov.b64 %0, {%1, %2};" : "=l"(r) : "f"(a), "f"(b));
    return r;
}
__device__ __forceinline__ float2 upk2(ull v) {
    float2 f;
    asm("mov.b64 {%0, %1}, %2;" : "=f"(f.x), "=f"(f.y) : "l"(v));
    return f;
}
__device__ __forceinline__ void ffma2(ull& d, ull a, ull b) {
    asm("fma.rn.f32x2 %0, %1, %2, %3;" : "=l"(d) : "l"(a), "l"(b), "l"(d));
}
__device__ __forceinline__ int load_idx(const void* p, long i, int is64) {
    if (is64) return (int)((const long long*)p)[i];
    return ((const int*)p)[i];
}
__device__ __forceinline__ void red_add_v4(float* addr, float4 v) {
    size_t ga = __cvta_generic_to_global(addr);
    asm volatile("red.global.add.v4.f32 [%0], {%1, %2, %3, %4};"
                 :: "l"(ga), "f"(v.x), "f"(v.y), "f"(v.z), "f"(v.w) : "memory");
}

// ------- rank pass: degree histogram + per-edge rank + dtype detect ---------
__global__ void rank_k(const void* __restrict__ ei, int E) {
    __shared__ int s64;
    if (threadIdx.x == 0) {
        const ull* e = (const ull*)ei;
        int f = 1;
#pragma unroll
        for (int i = 0; i < 16; i++)
            if (e[i] >> 32) f = 0;
        s64 = f;
        if (blockIdx.x == 0) g_is64 = f;
    }
    if (blockIdx.x == 0 && threadIdx.x < 64) g_bsum[threadIdx.x] = 0;
    __syncthreads();
    int is64 = s64;
    long base = ((long)blockIdx.x * blockDim.x + threadIdx.x) * 8;
#pragma unroll
    for (int j = 0; j < 8; j++) {
        long e = base + j;
        if (e < E) {
            int d = load_idx(ei, (long)E + e, is64);
            g_rank[e] = atomicAdd(&g_degi[d], 1);
        }
    }
}

// ------- single-pass scan with decoupled lookback; restores g_degi=0 --------
__global__ void scan_k(int n, int nblk) {
    cudaGridDependencySynchronize();
    __shared__ int wsum[32];
    __shared__ int s_carry;
    const int tid = threadIdx.x, lane = tid & 31, w = tid >> 5;
    const int b = blockIdx.x;
    int i = b * 1024 + tid;
    int v = (i < n) ? g_degi[i] : 0;
    if (i < n) g_degi[i] = 0;          // restore zero-invariant
    int x = v;
#pragma unroll
    for (int o = 1; o < 32; o <<= 1) {
        int y = __shfl_up_sync(~0u, x, o);
        if (lane >= o) x += y;
    }
    if (lane == 31) wsum[w] = x;
    __syncthreads();
    if (w == 0) {
        int s = wsum[lane];
#pragma unroll
        for (int o = 1; o < 32; o <<= 1) {
            int y = __shfl_up_sync(~0u, s, o);
            if (lane >= o) s += y;
        }
        wsum[lane] = s;
    }
    __syncthreads();
    int pre = (w > 0) ? wsum[w - 1] : 0;
    int incl = pre + x;
    int btotal = wsum[31];
    if (tid == 0) atomicExch(&g_bsum[b], btotal + 1);
    if (w == 0) {
        int sum = 0;
        for (int base = 0; base < b; base += 32) {
            int idx = base + lane;
            int val = 0;
            if (idx < b) {
                do { val = atomicAdd(&g_bsum[idx], 0); } while (val == 0);
                sum += val - 1;
            }
        }
#pragma unroll
        for (int o = 16; o; o >>= 1)
            sum += __shfl_down_sync(~0u, sum, o);
        if (lane == 0) s_carry = sum;
    }
    __syncthreads();
    int bpre = s_carry;
    if (i < n) {
        g_off[i] = bpre + incl - v;
        g_dinv[i] = rsqrtf((float)v + 1.0f);
    }
    if (b == nblk - 1 && tid == 1023) g_off[n] = bpre + incl;
}

// ---------- CSR fill: NO atomics. PDL: pre-load edge list before gridsync ---
__global__ void fill2_k(const void* __restrict__ ei, int E) {
    __shared__ int s64;
    if (threadIdx.x == 0) {
        const ull* e = (const ull*)ei;
        int f = 1;
#pragma unroll
        for (int i = 0; i < 16; i++)
            if (e[i] >> 32) f = 0;
        s64 = f;
    }
    __syncthreads();
    int is64 = s64;
    long base = ((long)blockIdx.x * blockDim.x + threadIdx.x) * 8;
    int s[8], d[8];
#pragma unroll
    for (int j = 0; j < 8; j++) {
        long e = base + j;
        if (e < E) {
            s[j] = load_idx(ei, e, is64);
            d[j] = load_idx(ei, (long)E + e, is64);
        } else d[j] = -1;
    }
    cudaGridDependencySynchronize();
#pragma unroll
    for (int j = 0; j < 8; j++) {
        long e = base + j;
        if (d[j] >= 0) g_csr[g_off[d[j]] + g_rank[e]] = s[j];
    }
}

// ------ gather-reduce over 128 cols: warp per dst node, 8-edge ILP ---------
// MODE 1: out = dinv_d * relu(dinv_d*(sum dinv_s*v_s + dinv_d*v_d) + bias)
// MODE 2: out = dinv_d * (sum v_s + v_d)   (inputs pre-scaled)
template <int MODE>
__global__ void gather128_k(const float* __restrict__ feat,
                            const float* __restrict__ bias,
                            float* __restrict__ out, int start, int end) {
    int node = start + blockIdx.x * (blockDim.x >> 5) + (threadIdx.x >> 5);
    if (node >= end) {
        cudaGridDependencySynchronize();
        return;
    }
    const int lane = threadIdx.x & 31;
    int p = g_off[node], pend = g_off[node + 1];   // ancient data: pre-sync safe
    float dd = g_dinv[node];
    cudaGridDependencySynchronize();               // feat = predecessor output
    const float4* f4 = (const float4*)feat;

    float4 acc = make_float4(0.f, 0.f, 0.f, 0.f);
    for (; p + 8 <= pend; p += 8) {
        int s[8]; float4 v[8];
#pragma unroll
        for (int j = 0; j < 8; j++) s[j] = __ldg(&g_csr[p + j]);
#pragma unroll
        for (int j = 0; j < 8; j++) v[j] = __ldg(&f4[(long)s[j] * 32 + lane]);
        if (MODE == 1) {
            float nn[8];
#pragma unroll
            for (int j = 0; j < 8; j++) nn[j] = __ldg(&g_dinv[s[j]]);
#pragma unroll
            for (int j = 0; j < 8; j++) {
                acc.x = fmaf(v[j].x, nn[j], acc.x);
                acc.y = fmaf(v[j].y, nn[j], acc.y);
                acc.z = fmaf(v[j].z, nn[j], acc.z);
                acc.w = fmaf(v[j].w, nn[j], acc.w);
            }
        } else {
#pragma unroll
            for (int j = 0; j < 8; j++) {
                acc.x += v[j].x; acc.y += v[j].y;
                acc.z += v[j].z; acc.w += v[j].w;
            }
        }
    }
    if (p + 4 <= pend) {
        int s[4]; float4 v[4];
#pragma unroll
        for (int j = 0; j < 4; j++) s[j] = __ldg(&g_csr[p + j]);
#pragma unroll
        for (int j = 0; j < 4; j++) v[j] = __ldg(&f4[(long)s[j] * 32 + lane]);
        if (MODE == 1) {
            float nn[4];
#pragma unroll
            for (int j = 0; j < 4; j++) nn[j] = __ldg(&g_dinv[s[j]]);
#pragma unroll
            for (int j = 0; j < 4; j++) {
                acc.x = fmaf(v[j].x, nn[j], acc.x);
                acc.y = fmaf(v[j].y, nn[j], acc.y);
                acc.z = fmaf(v[j].z, nn[j], acc.z);
                acc.w = fmaf(v[j].w, nn[j], acc.w);
            }
        } else {
#pragma unroll
            for (int j = 0; j < 4; j++) {
                acc.x += v[j].x; acc.y += v[j].y;
                acc.z += v[j].z; acc.w += v[j].w;
            }
        }
        p += 4;
    }
    for (; p < pend; p++) {
        int s0 = __ldg(&g_csr[p]);
        float4 v0 = __ldg(&f4[(long)s0 * 32 + lane]);
        if (MODE == 1) {
            float n0 = __ldg(&g_dinv[s0]);
            acc.x = fmaf(v0.x, n0, acc.x); acc.y = fmaf(v0.y, n0, acc.y);
            acc.z = fmaf(v0.z, n0, acc.z); acc.w = fmaf(v0.w, n0, acc.w);
        } else {
            acc.x += v0.x; acc.y += v0.y; acc.z += v0.z; acc.w += v0.w;
        }
    }
    float4 sv = __ldg(&f4[(long)node * 32 + lane]);
    if (MODE == 1) {
        acc.x = fmaf(sv.x, dd, acc.x); acc.y = fmaf(sv.y, dd, acc.y);
        acc.z = fmaf(sv.z, dd, acc.z); acc.w = fmaf(sv.w, dd, acc.w);
        float4 bb = __ldg(&((const float4*)bias)[lane]);
        acc.x = dd * fmaxf(fmaf(acc.x, dd, bb.x), 0.f);
        acc.y = dd * fmaxf(fmaf(acc.y, dd, bb.y), 0.f);
        acc.z = dd * fmaxf(fmaf(acc.z, dd, bb.z), 0.f);
        acc.w = dd * fmaxf(fmaf(acc.w, dd, bb.w), 0.f);
    } else {
        acc.x = dd * (acc.x + sv.x);
        acc.y = dd * (acc.y + sv.y);
        acc.z = dd * (acc.z + sv.z);
        acc.w = dd * (acc.w + sv.w);
    }
    ((float4*)out)[(long)node * 32 + lane] = acc;
}

// ------- layer-2 gemm + pool over rows [row0,rowend) -------------------------
// Stages the ENTIRE X half into smem right after gridsync, then triggers
// programmatic completion EARLY so the next gather chunk overlaps the FFMA phase.
__global__ void gemmpool_k(const float* __restrict__ X, const float* __restrict__ W,
                           const float* __restrict__ bias,
                           const void* __restrict__ batch, int row0, int rowend) {
    __shared__ ulonglong2 Ws2[32 * 32];   // 16 KB, restaged per kt
    __shared__ float Xs[64 * 128];        // 32 KB, staged once
    const int tid  = threadIdx.x;
    const int lane = tid & 31;
    const int warp = tid >> 5;
    const int rbase = row0 + blockIdx.x * 64;

    // stage W tile kt=0 pre-sync (stable input)
#pragma unroll
    for (int q = 0; q < 4; q++) {
        int f = tid + q * 256;
        float4 w = __ldg(&((const float4*)W)[f]);
        Ws2[f] = make_ulonglong2(pk2(w.x, w.y), pk2(w.z, w.w));
    }
    cudaGridDependencySynchronize();

    // stage all X rows (64 x 128 floats = 2048 float4, 8 per thread)
#pragma unroll
    for (int q = 0; q < 8; q++) {
        int f = tid + q * 256;
        int row = f >> 5;          // 32 float4 per row
        int c4 = f & 31;
        int gr = rbase + row;
        float4 v = make_float4(0.f, 0.f, 0.f, 0.f);
        if (gr < rowend)
            v = *(const float4*)(X + (long)gr * HID + c4 * 4);
        ((float4*)Xs)[f] = v;
    }
    __syncthreads();
    cudaTriggerProgrammaticLaunchCompletion();   // release next chunk's gather

    ull acc[8][2];
#pragma unroll
    for (int r = 0; r < 8; r++) { acc[r][0] = 0ull; acc[r][1] = 0ull; }

    for (int kt = 0; kt < 4; kt++) {
        if (kt > 0) {
            __syncthreads();
#pragma unroll
            for (int q = 0; q < 4; q++) {
                int f = tid + q * 256;
                float4 w = __ldg(&((const float4*)W)[kt * 1024 + f]);
                Ws2[f] = make_ulonglong2(pk2(w.x, w.y), pk2(w.z, w.w));
            }
            __syncthreads();
        }
#pragma unroll
        for (int k = 0; k < 32; k++) {
            ulonglong2 w2 = Ws2[k * 32 + lane];
#pragma unroll
            for (int r = 0; r < 8; r++) {
                float xs = Xs[(warp * 8 + r) * 128 + kt * 32 + k];
                ull xx = pk2(xs, xs);
                ffma2(acc[r][0], xx, w2.x);
                ffma2(acc[r][1], xx, w2.y);
            }
        }
    }
    float4 bb = __ldg(&((const float4*)bias)[lane]);
    int is64 = g_is64;
#pragma unroll
    for (int r = 0; r < 8; r++) {
        int row = rbase + warp * 8 + r;
        if (row < rowend) {
            float2 a = upk2(acc[r][0]);
            float2 b = upk2(acc[r][1]);
            float4 o;
            o.x = fmaxf(a.x + bb.x, 0.f);
            o.y = fmaxf(a.y + bb.y, 0.f);
            o.z = fmaxf(b.x + bb.z, 0.f);
            o.w = fmaxf(b.y + bb.w, 0.f);
            int g = load_idx(batch, row, is64);
            red_add_v4(g_sums + (long)g * HID + lane * 4, o);
            if (lane == 0) atomicAdd(&g_cnt[g], 1.0f);
        }
    }
}

// ------- layer-1 fork gemm: h1 = X @ W1, plain store ------------------------
__global__ void gemm96_k(const float* __restrict__ X, const float* __restrict__ W,
                         float* __restrict__ out, int n) {
    __shared__ ulonglong2 Ws2[32 * 32];
    __shared__ ull Xs2[64 * 32];
    const int tid  = threadIdx.x;
    const int lane = tid & 31;
    const int warp = tid >> 5;
    const int rbase = blockIdx.x * 64;

    ull acc[8][2];
#pragma unroll
    for (int r = 0; r < 8; r++) { acc[r][0] = 0ull; acc[r][1] = 0ull; }

    for (int kt = 0; kt < 3; kt++) {
#pragma unroll
        for (int j = 0; j < 4; j++) {
            int f = tid + j * 256;
            float4 w = __ldg(&((const float4*)W)[kt * 1024 + f]);
            Ws2[f] = make_ulonglong2(pk2(w.x, w.y), pk2(w.z, w.w));
        }
#pragma unroll
        for (int j = 0; j < 2; j++) {
            int f = tid + j * 256;
            int row = f >> 3;
            int kq = f & 7;
            int gr = rbase + row;
            float4 v = make_float4(0.f, 0.f, 0.f, 0.f);
            if (gr < n)
                v = *(const float4*)(X + (long)gr * 96 + kt * 32 + kq * 4);
            int bb = row * 32 + kq * 4;
            Xs2[bb + 0] = pk2(v.x, v.x);
            Xs2[bb + 1] = pk2(v.y, v.y);
            Xs2[bb + 2] = pk2(v.z, v.z);
            Xs2[bb + 3] = pk2(v.w, v.w);
        }
        __syncthreads();
#pragma unroll
        for (int k = 0; k < 32; k++) {
            ulonglong2 w2 = Ws2[k * 32 + lane];
#pragma unroll
            for (int r = 0; r < 8; r++) {
                ull xx = Xs2[(warp * 8 + r) * 32 + k];
                ffma2(acc[r][0], xx, w2.x);
                ffma2(acc[r][1], xx, w2.y);
            }
        }
        __syncthreads();
    }
#pragma unroll
    for (int r = 0; r < 8; r++) {
        int row = rbase + warp * 8 + r;
        if (row < n) {
            float2 a = upk2(acc[r][0]);
            float2 b = upk2(acc[r][1]);
            *(float4*)(out + (long)row * HID + lane * 4) =
                make_float4(a.x, a.y, b.x, b.y);
        }
    }
}

// ------- mean + final linear (+ zero-restore); NORMAL launch ----------------
__global__ void final_k(const float* __restrict__ Wlin, const float* __restrict__ blin,
                        float* __restrict__ out) {
    int g = blockIdx.x;
    int t = threadIdx.x;  // 128
    float c = fmaxf(g_cnt[g], 1.0f);
    float s = g_sums[g * HID + t] / c;
    g_sums[g * HID + t] = 0.f;
    if (t == 0) g_cnt[g] = 0.f;
    float p0 = s * Wlin[2 * t];
    float p1 = s * Wlin[2 * t + 1];
#pragma unroll
    for (int off = 16; off; off >>= 1) {
        p0 += __shfl_down_sync(0xffffffffu, p0, off);
        p1 += __shfl_down_sync(0xffffffffu, p1, off);
    }
    __shared__ float s0[4], s1[4];
    int w = t >> 5;
    if ((t & 31) == 0) { s0[w] = p0; s1[w] = p1; }
    __syncthreads();
    if (t == 0) {
        out[g * 2 + 0] = s0[0] + s0[1] + s0[2] + s0[3] + blin[0];
        out[g * 2 + 1] = s1[0] + s1[1] + s1[2] + s1[3] + blin[1];
    }
}

// ---------------- PDL launch helper ----------------
template <typename F, typename... Args>
static void launch_pdl(F f, dim3 grid, dim3 block, cudaStream_t st, Args... args) {
    cudaLaunchConfig_t cfg = {};
    cfg.gridDim = grid;
    cfg.blockDim = block;
    cfg.dynamicSmemBytes = 0;
    cfg.stream = st;
    cudaLaunchAttribute attr[1];
    attr[0].id = cudaLaunchAttributeProgrammaticStreamSerialization;
    attr[0].val.programmaticStreamSerializationAllowed = 1;
    cfg.attrs = attr;
    cfg.numAttrs = 1;
    cudaLaunchKernelEx(&cfg, f, args...);
}

// ---------------- launcher ----------------
extern "C" void kernel_launch(void* const* d_in, const int* in_sizes, int n_in,
                              void* d_out, int out_size) {
    (void)out_size;
    const float* x     = (const float*)d_in[0];
    const void*  ei    = d_in[1];
    const void*  batch = d_in[2];
    int base = (n_in >= 10) ? 4 : 3;
    const float* W1   = (const float*)d_in[base + 0];
    const float* b1   = (const float*)d_in[base + 1];
    const float* W2   = (const float*)d_in[base + 2];
    const float* b2   = (const float*)d_in[base + 3];
    const float* Wlin = (const float*)d_in[base + 4];
    const float* blin = (const float*)d_in[base + 5];

    const int N = in_sizes[0] / 96;
    const int E = in_sizes[1] / 2;
    const int NBLK = (N + 1023) >> 10;  // <= 49
    float* out = (float*)d_out;

    static cudaStream_t s1 = 0;
    static cudaEvent_t evF, evJ;
    if (!s1) {
        cudaStreamCreateWithFlags(&s1, cudaStreamNonBlocking);
        cudaEventCreateWithFlags(&evF, cudaEventDisableTiming);
        cudaEventCreateWithFlags(&evJ, cudaEventDisableTiming);
    }

    void *p_a, *p_h;
    cudaGetSymbolAddress(&p_a, g_a);
    cudaGetSymbolAddress(&p_h, g_h);

    int M = ((N / 2 + 63) / 64) * 64;   // 64-aligned half split
    if (M > N) M = N;

    // fork: h1 = x @ W1 on s1 (independent of graph prep)
    cudaEventRecord(evF, 0);
    cudaStreamWaitEvent(s1, evF, 0);
    gemm96_k<<<(N + 63) / 64, 256, 0, s1>>>(x, W1, (float*)p_h, N);
    cudaEventRecord(evJ, s1);

    // prep chain on stream 0 (no memsets; PDL-overlapped boundaries)
    rank_k<<<(E + 2047) / 2048, 256>>>(ei, E);
    launch_pdl(scan_k, dim3(NBLK), dim3(1024), (cudaStream_t)0, N, NBLK);
    launch_pdl(fill2_k, dim3((E + 2047) / 2048), dim3(256), (cudaStream_t)0,
               ei, E);

    // join gemm96, then layer-1 gather (PDL w.r.t. fill2; event wait enforced)
    cudaStreamWaitEvent(0, evJ, 0);
    launch_pdl(gather128_k<1>, dim3((N + 7) / 8), dim3(256), (cudaStream_t)0,
               (const float*)p_h, b1, (float*)p_a, 0, N);

    // layer 2, chunked with early-trigger overlap:
    //   gatherA -> gemmA(stage X, trigger, FFMA) || gatherB -> gemmB
    launch_pdl(gather128_k<2>, dim3((M + 7) / 8), dim3(256), (cudaStream_t)0,
               (const float*)p_a, (const float*)nullptr, (float*)p_h, 0, M);
    launch_pdl(gemmpool_k, dim3((M + 63) / 64), dim3(256), (cudaStream_t)0,
               (const float*)p_h, W2, b2, (const void*)batch, 0, M);
    if (M < N) {
        launch_pdl(gather128_k<2>, dim3((N - M + 7) / 8), dim3(256),
                   (cudaStream_t)0,
                   (const float*)p_a, (const float*)nullptr, (float*)p_h, M, N);
        launch_pdl(gemmpool_k, dim3((N - M + 63) / 64), dim3(256),
                   (cudaStream_t)0,
                   (const float*)p_h, W2, b2, (const void*)batch, M, N);
    }

    // NORMAL launch: full stream barrier covers gemmA's post-trigger epilogue
    final_k<<<N_GRAPHS, HID>>>(Wlin, blin, out);
}

// round 15
// speedup vs baseline: 1.1362x; 1.0226x over previous
#include <cuda_runtime.h>
#include <math.h>

#define N_NODES_MAX 50000
#define E_MAX 800000
#define N_GRAPHS 512
#define HID 128

typedef unsigned long long ull;

// ------------- scratch (zero at load; zero-invariants maintained) ----------
__device__ float g_h[(size_t)N_NODES_MAX * HID];    // xW1 / gather2 out
__device__ float g_a[(size_t)N_NODES_MAX * HID];    // act1' (pre-scaled)
__device__ int   g_degi[N_NODES_MAX];               // INVARIANT: zero between calls
__device__ int   g_off[N_NODES_MAX + 1];
__device__ float g_dinv[N_NODES_MAX];               // 1/sqrt(deg+1)
__device__ int   g_rank[E_MAX];                     // per-edge rank within dst
__device__ int   g_csr[E_MAX];                      // src ids grouped by dst
__device__ int   g_bsum[64];                        // zeroed by rank_k block 0
__device__ float g_sums[N_GRAPHS * HID];            // INVARIANT: zero between calls
__device__ float g_cnt[N_GRAPHS];                   // INVARIANT: zero between calls
__device__ int   g_is64;

// ---------------- packed f32x2 helpers ----------------
__device__ __forceinline__ ull pk2(float a, float b) {
    ull r;
    asm("mov.b64 %0, {%1, %2};" : "=l"(r) : "f"(a), "f"(b));
    return r;
}
__device__ __forceinline__ float2 upk2(ull v) {
    float2 f;
    asm("mov.b64 {%0, %1}, %2;" : "=f"(f.x), "=f"(f.y) : "l"(v));
    return f;
}
__device__ __forceinline__ void ffma2(ull& d, ull a, ull b) {
    asm("fma.rn.f32x2 %0, %1, %2, %3;" : "=l"(d) : "l"(a), "l"(b), "l"(d));
}
__device__ __forceinline__ int load_idx(const void* p, long i, int is64) {
    if (is64) return (int)((const long long*)p)[i];
    return ((const int*)p)[i];
}
__device__ __forceinline__ void red_add_v4(float* addr, float4 v) {
    size_t ga = __cvta_generic_to_global(addr);
    asm volatile("red.global.add.v4.f32 [%0], {%1, %2, %3, %4};"
                 :: "l"(ga), "f"(v.x), "f"(v.y), "f"(v.z), "f"(v.w) : "memory");
}

// ------- rank pass: degree histogram + per-edge rank + dtype detect ---------
__global__ void rank_k(const void* __restrict__ ei, int E) {
    __shared__ int s64;
    if (threadIdx.x == 0) {
        const ull* e = (const ull*)ei;
        int f = 1;
#pragma unroll
        for (int i = 0; i < 16; i++)
            if (e[i] >> 32) f = 0;
        s64 = f;
        if (blockIdx.x == 0) g_is64 = f;
    }
    if (blockIdx.x == 0 && threadIdx.x < 64) g_bsum[threadIdx.x] = 0;
    __syncthreads();
    int is64 = s64;
    long base = ((long)blockIdx.x * blockDim.x + threadIdx.x) * 8;
#pragma unroll
    for (int j = 0; j < 8; j++) {
        long e = base + j;
        if (e < E) {
            int d = load_idx(ei, (long)E + e, is64);
            g_rank[e] = atomicAdd(&g_degi[d], 1);
        }
    }
}

// ------- single-pass scan with decoupled lookback; restores g_degi=0 --------
__global__ void scan_k(int n, int nblk) {
    cudaGridDependencySynchronize();
    __shared__ int wsum[32];
    __shared__ int s_carry;
    const int tid = threadIdx.x, lane = tid & 31, w = tid >> 5;
    const int b = blockIdx.x;
    int i = b * 1024 + tid;
    int v = (i < n) ? g_degi[i] : 0;
    if (i < n) g_degi[i] = 0;          // restore zero-invariant
    int x = v;
#pragma unroll
    for (int o = 1; o < 32; o <<= 1) {
        int y = __shfl_up_sync(~0u, x, o);
        if (lane >= o) x += y;
    }
    if (lane == 31) wsum[w] = x;
    __syncthreads();
    if (w == 0) {
        int s = wsum[lane];
#pragma unroll
        for (int o = 1; o < 32; o <<= 1) {
            int y = __shfl_up_sync(~0u, s, o);
            if (lane >= o) s += y;
        }
        wsum[lane] = s;
    }
    __syncthreads();
    int pre = (w > 0) ? wsum[w - 1] : 0;
    int incl = pre + x;
    int btotal = wsum[31];
    if (tid == 0) atomicExch(&g_bsum[b], btotal + 1);
    if (w == 0) {
        int sum = 0;
        for (int base = 0; base < b; base += 32) {
            int idx = base + lane;
            int val = 0;
            if (idx < b) {
                do { val = atomicAdd(&g_bsum[idx], 0); } while (val == 0);
                sum += val - 1;
            }
        }
#pragma unroll
        for (int o = 16; o; o >>= 1)
            sum += __shfl_down_sync(~0u, sum, o);
        if (lane == 0) s_carry = sum;
    }
    __syncthreads();
    int bpre = s_carry;
    if (i < n) {
        g_off[i] = bpre + incl - v;
        g_dinv[i] = rsqrtf((float)v + 1.0f);
    }
    if (b == nblk - 1 && tid == 1023) g_off[n] = bpre + incl;
}

// ---------- CSR fill: NO atomics. PDL: pre-load edge list before gridsync ---
__global__ void fill2_k(const void* __restrict__ ei, int E) {
    __shared__ int s64;
    if (threadIdx.x == 0) {
        const ull* e = (const ull*)ei;
        int f = 1;
#pragma unroll
        for (int i = 0; i < 16; i++)
            if (e[i] >> 32) f = 0;
        s64 = f;
    }
    __syncthreads();
    int is64 = s64;
    long base = ((long)blockIdx.x * blockDim.x + threadIdx.x) * 8;
    int s[8], d[8];
#pragma unroll
    for (int j = 0; j < 8; j++) {
        long e = base + j;
        if (e < E) {
            s[j] = load_idx(ei, e, is64);
            d[j] = load_idx(ei, (long)E + e, is64);
        } else d[j] = -1;
    }
    cudaGridDependencySynchronize();
#pragma unroll
    for (int j = 0; j < 8; j++) {
        long e = base + j;
        if (d[j] >= 0) g_csr[g_off[d[j]] + g_rank[e]] = s[j];
    }
}

// ------ gather-reduce over 128 cols: warp per dst node, 8-edge ILP ---------
// MODE 1: out = dinv_d * relu(dinv_d*(sum dinv_s*v_s + dinv_d*v_d) + bias)
// MODE 2: out = dinv_d * (sum v_s + v_d)   (inputs pre-scaled)
template <int MODE>
__global__ void gather128_k(const float* __restrict__ feat,
                            const float* __restrict__ bias,
                            float* __restrict__ out, int n) {
    int node = blockIdx.x * (blockDim.x >> 5) + (threadIdx.x >> 5);
    if (node >= n) {
        cudaGridDependencySynchronize();
        return;
    }
    const int lane = threadIdx.x & 31;
    int p = g_off[node], pend = g_off[node + 1];   // ancient data: pre-sync safe
    float dd = g_dinv[node];
    cudaGridDependencySynchronize();               // feat = predecessor output
    const float4* f4 = (const float4*)feat;

    float4 acc = make_float4(0.f, 0.f, 0.f, 0.f);
    for (; p + 8 <= pend; p += 8) {
        int s[8]; float4 v[8];
#pragma unroll
        for (int j = 0; j < 8; j++) s[j] = __ldg(&g_csr[p + j]);
#pragma unroll
        for (int j = 0; j < 8; j++) v[j] = __ldg(&f4[(long)s[j] * 32 + lane]);
        if (MODE == 1) {
            float nn[8];
#pragma unroll
            for (int j = 0; j < 8; j++) nn[j] = __ldg(&g_dinv[s[j]]);
#pragma unroll
            for (int j = 0; j < 8; j++) {
                acc.x = fmaf(v[j].x, nn[j], acc.x);
                acc.y = fmaf(v[j].y, nn[j], acc.y);
                acc.z = fmaf(v[j].z, nn[j], acc.z);
                acc.w = fmaf(v[j].w, nn[j], acc.w);
            }
        } else {
#pragma unroll
            for (int j = 0; j < 8; j++) {
                acc.x += v[j].x; acc.y += v[j].y;
                acc.z += v[j].z; acc.w += v[j].w;
            }
        }
    }
    if (p + 4 <= pend) {
        int s[4]; float4 v[4];
#pragma unroll
        for (int j = 0; j < 4; j++) s[j] = __ldg(&g_csr[p + j]);
#pragma unroll
        for (int j = 0; j < 4; j++) v[j] = __ldg(&f4[(long)s[j] * 32 + lane]);
        if (MODE == 1) {
            float nn[4];
#pragma unroll
            for (int j = 0; j < 4; j++) nn[j] = __ldg(&g_dinv[s[j]]);
#pragma unroll
            for (int j = 0; j < 4; j++) {
                acc.x = fmaf(v[j].x, nn[j], acc.x);
                acc.y = fmaf(v[j].y, nn[j], acc.y);
                acc.z = fmaf(v[j].z, nn[j], acc.z);
                acc.w = fmaf(v[j].w, nn[j], acc.w);
            }
        } else {
#pragma unroll
            for (int j = 0; j < 4; j++) {
                acc.x += v[j].x; acc.y += v[j].y;
                acc.z += v[j].z; acc.w += v[j].w;
            }
        }
        p += 4;
    }
    for (; p < pend; p++) {
        int s0 = __ldg(&g_csr[p]);
        float4 v0 = __ldg(&f4[(long)s0 * 32 + lane]);
        if (MODE == 1) {
            float n0 = __ldg(&g_dinv[s0]);
            acc.x = fmaf(v0.x, n0, acc.x); acc.y = fmaf(v0.y, n0, acc.y);
            acc.z = fmaf(v0.z, n0, acc.z); acc.w = fmaf(v0.w, n0, acc.w);
        } else {
            acc.x += v0.x; acc.y += v0.y; acc.z += v0.z; acc.w += v0.w;
        }
    }
    float4 sv = __ldg(&f4[(long)node * 32 + lane]);
    if (MODE == 1) {
        acc.x = fmaf(sv.x, dd, acc.x); acc.y = fmaf(sv.y, dd, acc.y);
        acc.z = fmaf(sv.z, dd, acc.z); acc.w = fmaf(sv.w, dd, acc.w);
        float4 bb = __ldg(&((const float4*)bias)[lane]);
        acc.x = dd * fmaxf(fmaf(acc.x, dd, bb.x), 0.f);
        acc.y = dd * fmaxf(fmaf(acc.y, dd, bb.y), 0.f);
        acc.z = dd * fmaxf(fmaf(acc.z, dd, bb.z), 0.f);
        acc.w = dd * fmaxf(fmaf(acc.w, dd, bb.w), 0.f);
    } else {
        acc.x = dd * (acc.x + sv.x);
        acc.y = dd * (acc.y + sv.y);
        acc.z = dd * (acc.z + sv.z);
        acc.w = dd * (acc.w + sv.w);
    }
    ((float4*)out)[(long)node * 32 + lane] = acc;
}

// ------- dense transform: [rows,KIN] @ [KIN,128] ----------------------------
// EPI_MODE 0: plain store. 2: bias+relu+pool-reduce into g_sums/g_cnt.
// PDL: W tile for kt=0 staged pre-sync (W is a stable input); X post-sync.
template <int KIN, int EPI_MODE>
__global__ void gemm_k(const float* __restrict__ X, const float* __restrict__ W,
                       const float* __restrict__ bias, float* __restrict__ out,
                       const void* __restrict__ batch, int n) {
    __shared__ ulonglong2 Ws2[32 * 32];
    __shared__ ull Xs2[64 * 32];
    const int tid  = threadIdx.x;
    const int lane = tid & 31;
    const int warp = tid >> 5;
    const int rbase = blockIdx.x * 64;

    ull acc[8][2];
#pragma unroll
    for (int r = 0; r < 8; r++) { acc[r][0] = 0ull; acc[r][1] = 0ull; }

    const int KT = KIN / 32;
    for (int kt = 0; kt < KT; kt++) {
#pragma unroll
        for (int j = 0; j < 4; j++) {
            int f = tid + j * 256;
            float4 w = __ldg(&((const float4*)W)[kt * 1024 + f]);
            Ws2[f] = make_ulonglong2(pk2(w.x, w.y), pk2(w.z, w.w));
        }
        if (kt == 0) cudaGridDependencySynchronize();
#pragma unroll
        for (int j = 0; j < 2; j++) {
            int f = tid + j * 256;
            int row = f >> 3;
            int kq = f & 7;
            int gr = rbase + row;
            float4 v = make_float4(0.f, 0.f, 0.f, 0.f);
            if (gr < n)
                v = *(const float4*)(X + (long)gr * KIN + kt * 32 + kq * 4);
            int bb = row * 32 + kq * 4;
            Xs2[bb + 0] = pk2(v.x, v.x);
            Xs2[bb + 1] = pk2(v.y, v.y);
            Xs2[bb + 2] = pk2(v.z, v.z);
            Xs2[bb + 3] = pk2(v.w, v.w);
        }
        __syncthreads();
#pragma unroll
        for (int k = 0; k < 32; k++) {
            ulonglong2 w2 = Ws2[k * 32 + lane];
#pragma unroll
            for (int r = 0; r < 8; r++) {
                ull xx = Xs2[(warp * 8 + r) * 32 + k];
                ffma2(acc[r][0], xx, w2.x);
                ffma2(acc[r][1], xx, w2.y);
            }
        }
        __syncthreads();
    }
    float4 bb = make_float4(0.f, 0.f, 0.f, 0.f);
    if (EPI_MODE == 2) bb = __ldg(&((const float4*)bias)[lane]);
    int is64 = (EPI_MODE == 2) ? g_is64 : 0;
#pragma unroll
    for (int r = 0; r < 8; r++) {
        int row = rbase + warp * 8 + r;
        if (row < n) {
            float2 a = upk2(acc[r][0]);
            float2 b = upk2(acc[r][1]);
            if (EPI_MODE == 0) {
                *(float4*)(out + (long)row * HID + lane * 4) =
                    make_float4(a.x, a.y, b.x, b.y);
            } else {
                float4 o;
                o.x = fmaxf(a.x + bb.x, 0.f);
                o.y = fmaxf(a.y + bb.y, 0.f);
                o.z = fmaxf(b.x + bb.z, 0.f);
                o.w = fmaxf(b.y + bb.w, 0.f);
                int g = load_idx(batch, row, is64);
                red_add_v4(g_sums + (long)g * HID + lane * 4, o);
                if (lane == 0) atomicAdd(&g_cnt[g], 1.0f);
            }
        }
    }
}

// ------- mean + final linear (+ zero-restore g_sums/g_cnt); PDL-synced ------
__global__ void final_k(const float* __restrict__ Wlin, const float* __restrict__ blin,
                        float* __restrict__ out) {
    int g = blockIdx.x;
    int t = threadIdx.x;  // 128
    float w0 = Wlin[2 * t], w1 = Wlin[2 * t + 1];   // stable inputs, pre-sync
    cudaGridDependencySynchronize();
    float c = fmaxf(g_cnt[g], 1.0f);
    float s = g_sums[g * HID + t] / c;
    g_sums[g * HID + t] = 0.f;        // restore zero-invariant
    if (t == 0) g_cnt[g] = 0.f;
    float p0 = s * w0;
    float p1 = s * w1;
#pragma unroll
    for (int off = 16; off; off >>= 1) {
        p0 += __shfl_down_sync(0xffffffffu, p0, off);
        p1 += __shfl_down_sync(0xffffffffu, p1, off);
    }
    __shared__ float s0[4], s1[4];
    int w = t >> 5;
    if ((t & 31) == 0) { s0[w] = p0; s1[w] = p1; }
    __syncthreads();
    if (t == 0) {
        out[g * 2 + 0] = s0[0] + s0[1] + s0[2] + s0[3] + blin[0];
        out[g * 2 + 1] = s1[0] + s1[1] + s1[2] + s1[3] + blin[1];
    }
}

// ---------------- PDL launch helper ----------------
template <typename F, typename... Args>
static void launch_pdl(F f, dim3 grid, dim3 block, cudaStream_t st, Args... args) {
    cudaLaunchConfig_t cfg = {};
    cfg.gridDim = grid;
    cfg.blockDim = block;
    cfg.dynamicSmemBytes = 0;
    cfg.stream = st;
    cudaLaunchAttribute attr[1];
    attr[0].id = cudaLaunchAttributeProgrammaticStreamSerialization;
    attr[0].val.programmaticStreamSerializationAllowed = 1;
    cfg.attrs = attr;
    cfg.numAttrs = 1;
    cudaLaunchKernelEx(&cfg, f, args...);
}

// ---------------- launcher ----------------
extern "C" void kernel_launch(void* const* d_in, const int* in_sizes, int n_in,
                              void* d_out, int out_size) {
    (void)out_size;
    const float* x     = (const float*)d_in[0];
    const void*  ei    = d_in[1];
    const void*  batch = d_in[2];
    int base = (n_in >= 10) ? 4 : 3;
    const float* W1   = (const float*)d_in[base + 0];
    const float* b1   = (const float*)d_in[base + 1];
    const float* W2   = (const float*)d_in[base + 2];
    const float* b2   = (const float*)d_in[base + 3];
    const float* Wlin = (const float*)d_in[base + 4];
    const float* blin = (const float*)d_in[base + 5];

    const int N = in_sizes[0] / 96;
    const int E = in_sizes[1] / 2;
    const int NBLK = (N + 1023) >> 10;  // <= 49
    float* out = (float*)d_out;

    static cudaStream_t s1 = 0;
    static cudaEvent_t evF, evJ;
    if (!s1) {
        cudaStreamCreateWithFlags(&s1, cudaStreamNonBlocking);
        cudaEventCreateWithFlags(&evF, cudaEventDisableTiming);
        cudaEventCreateWithFlags(&evJ, cudaEventDisableTiming);
    }

    void *p_a, *p_h;
    cudaGetSymbolAddress(&p_a, g_a);
    cudaGetSymbolAddress(&p_h, g_h);

    // fork: h1 = x @ W1 on s1 (independent of graph prep)
    cudaEventRecord(evF, 0);
    cudaStreamWaitEvent(s1, evF, 0);
    gemm_k<96, 0><<<(N + 63) / 64, 256, 0, s1>>>(x, W1, nullptr,
                                                 (float*)p_h, nullptr, N);
    cudaEventRecord(evJ, s1);

    // prep chain on stream 0 (no memsets; PDL-overlapped boundaries)
    rank_k<<<(E + 2047) / 2048, 256>>>(ei, E);
    launch_pdl(scan_k, dim3(NBLK), dim3(1024), (cudaStream_t)0, N, NBLK);
    launch_pdl(fill2_k, dim3((E + 2047) / 2048), dim3(256), (cudaStream_t)0,
               ei, E);

    // layer-1 gather: PDL w.r.t. fill2; gemm96 event edge stays a full barrier
    cudaStreamWaitEvent(0, evJ, 0);
    launch_pdl(gather128_k<1>, dim3((N + 7) / 8), dim3(256), (cudaStream_t)0,
               (const float*)p_h, b1, (float*)p_a, N);

    // layer 2: unweighted aggregate of act1' -> g_h, then gemm + pool (PDL)
    launch_pdl(gather128_k<2>, dim3((N + 7) / 8), dim3(256), (cudaStream_t)0,
               (const float*)p_a, (const float*)nullptr, (float*)p_h, N);
    launch_pdl(gemm_k<128, 2>, dim3((N + 63) / 64), dim3(256), (cudaStream_t)0,
               (const float*)p_h, W2, b2, (float*)nullptr, (const void*)batch, N);

    launch_pdl(final_k, dim3(N_GRAPHS), dim3(HID), (cudaStream_t)0,
               Wlin, blin, out);
}

// round 16
// speedup vs baseline: 1.2027x; 1.0586x over previous
#include <cuda_runtime.h>
#include <cuda_fp16.h>
#include <math.h>

#define N_NODES_MAX 50000
#define E_MAX 800000
#define N_GRAPHS 512
#define HID 128

typedef unsigned long long ull;

// ------------- scratch (zero at load; zero-invariants maintained) ----------
__device__ float  g_h[(size_t)N_NODES_MAX * HID];   // xW1 / gather2 out
__device__ __half g_a16[(size_t)N_NODES_MAX * HID]; // act1' (pre-scaled, fp16, >=0)
__device__ int    g_degi[N_NODES_MAX];              // INVARIANT: zero between calls
__device__ int    g_off[N_NODES_MAX + 1];
__device__ float  g_dinv[N_NODES_MAX];              // 1/sqrt(deg+1)
__device__ int    g_rank[E_MAX];                    // per-edge rank within dst
__device__ int    g_csr[E_MAX];                     // src ids grouped by dst
__device__ int    g_bsum[64];                       // zeroed by rank_k block 0
__device__ float  g_sums[N_GRAPHS * HID];           // INVARIANT: zero between calls
__device__ float  g_cnt[N_GRAPHS];                  // INVARIANT: zero between calls
__device__ int    g_is64;

// ---------------- packed f32x2 helpers ----------------
__device__ __forceinline__ ull pk2(float a, float b) {
    ull r;
    asm("mov.b64 %0, {%1, %2};" : "=l"(r) : "f"(a), "f"(b));
    return r;
}
__device__ __forceinline__ float2 upk2(ull v) {
    float2 f;
    asm("mov.b64 {%0, %1}, %2;" : "=f"(f.x), "=f"(f.y) : "l"(v));
    return f;
}
__device__ __forceinline__ void ffma2(ull& d, ull a, ull b) {
    asm("fma.rn.f32x2 %0, %1, %2, %3;" : "=l"(d) : "l"(a), "l"(b), "l"(d));
}
__device__ __forceinline__ int load_idx(const void* p, long i, int is64) {
    if (is64) return (int)((const long long*)p)[i];
    return ((const int*)p)[i];
}
__device__ __forceinline__ void red_add_v4(float* addr, float4 v) {
    size_t ga = __cvta_generic_to_global(addr);
    asm volatile("red.global.add.v4.f32 [%0], {%1, %2, %3, %4};"
                 :: "l"(ga), "f"(v.x), "f"(v.y), "f"(v.z), "f"(v.w) : "memory");
}

// ------- rank pass: degree histogram + per-edge rank + dtype detect ---------
__global__ void rank_k(const void* __restrict__ ei, int E) {
    __shared__ int s64;
    if (threadIdx.x == 0) {
        const ull* e = (const ull*)ei;
        int f = 1;
#pragma unroll
        for (int i = 0; i < 16; i++)
            if (e[i] >> 32) f = 0;
        s64 = f;
        if (blockIdx.x == 0) g_is64 = f;
    }
    if (blockIdx.x == 0 && threadIdx.x < 64) g_bsum[threadIdx.x] = 0;
    __syncthreads();
    int is64 = s64;
    long base = ((long)blockIdx.x * blockDim.x + threadIdx.x) * 8;
#pragma unroll
    for (int j = 0; j < 8; j++) {
        long e = base + j;
        if (e < E) {
            int d = load_idx(ei, (long)E + e, is64);
            g_rank[e] = atomicAdd(&g_degi[d], 1);
        }
    }
}

// ------- single-pass scan with decoupled lookback; restores g_degi=0 --------
__global__ void scan_k(int n, int nblk) {
    cudaGridDependencySynchronize();
    __shared__ int wsum[32];
    __shared__ int s_carry;
    const int tid = threadIdx.x, lane = tid & 31, w = tid >> 5;
    const int b = blockIdx.x;
    int i = b * 1024 + tid;
    int v = (i < n) ? g_degi[i] : 0;
    if (i < n) g_degi[i] = 0;
    int x = v;
#pragma unroll
    for (int o = 1; o < 32; o <<= 1) {
        int y = __shfl_up_sync(~0u, x, o);
        if (lane >= o) x += y;
    }
    if (lane == 31) wsum[w] = x;
    __syncthreads();
    if (w == 0) {
        int s = wsum[lane];
#pragma unroll
        for (int o = 1; o < 32; o <<= 1) {
            int y = __shfl_up_sync(~0u, s, o);
            if (lane >= o) s += y;
        }
        wsum[lane] = s;
    }
    __syncthreads();
    int pre = (w > 0) ? wsum[w - 1] : 0;
    int incl = pre + x;
    int btotal = wsum[31];
    if (tid == 0) atomicExch(&g_bsum[b], btotal + 1);
    if (w == 0) {
        int sum = 0;
        for (int base = 0; base < b; base += 32) {
            int idx = base + lane;
            int val = 0;
            if (idx < b) {
                do { val = atomicAdd(&g_bsum[idx], 0); } while (val == 0);
                sum += val - 1;
            }
        }
#pragma unroll
        for (int o = 16; o; o >>= 1)
            sum += __shfl_down_sync(~0u, sum, o);
        if (lane == 0) s_carry = sum;
    }
    __syncthreads();
    int bpre = s_carry;
    if (i < n) {
        g_off[i] = bpre + incl - v;
        g_dinv[i] = rsqrtf((float)v + 1.0f);
    }
    if (b == nblk - 1 && tid == 1023) g_off[n] = bpre + incl;
}

// ---------- CSR fill: NO atomics. PDL: pre-load edge list before gridsync ---
__global__ void fill2_k(const void* __restrict__ ei, int E) {
    __shared__ int s64;
    if (threadIdx.x == 0) {
        const ull* e = (const ull*)ei;
        int f = 1;
#pragma unroll
        for (int i = 0; i < 16; i++)
            if (e[i] >> 32) f = 0;
        s64 = f;
    }
    __syncthreads();
    int is64 = s64;
    long base = ((long)blockIdx.x * blockDim.x + threadIdx.x) * 8;
    int s[8], d[8];
#pragma unroll
    for (int j = 0; j < 8; j++) {
        long e = base + j;
        if (e < E) {
            s[j] = load_idx(ei, e, is64);
            d[j] = load_idx(ei, (long)E + e, is64);
        } else d[j] = -1;
    }
    cudaGridDependencySynchronize();
#pragma unroll
    for (int j = 0; j < 8; j++) {
        long e = base + j;
        if (d[j] >= 0) g_csr[g_off[d[j]] + g_rank[e]] = s[j];
    }
}

// ------ layer-1 gather (fp32 in, fp16 out): warp per dst node, 8-edge ILP ---
// out16 = half( dinv_d * relu(dinv_d*(sum dinv_s*v_s + dinv_d*v_d) + bias) )
__global__ void gather1_k(const float* __restrict__ feat,
                          const float* __restrict__ bias,
                          __half* __restrict__ out16, int n) {
    int node = blockIdx.x * (blockDim.x >> 5) + (threadIdx.x >> 5);
    if (node >= n) {
        cudaGridDependencySynchronize();
        return;
    }
    const int lane = threadIdx.x & 31;
    int p = g_off[node], pend = g_off[node + 1];   // ancient data: pre-sync safe
    float dd = g_dinv[node];
    cudaGridDependencySynchronize();               // feat = gemm96 output
    const float4* f4 = (const float4*)feat;

    float4 acc = make_float4(0.f, 0.f, 0.f, 0.f);
    for (; p + 8 <= pend; p += 8) {
        int s[8]; float4 v[8]; float nn[8];
#pragma unroll
        for (int j = 0; j < 8; j++) s[j] = __ldg(&g_csr[p + j]);
#pragma unroll
        for (int j = 0; j < 8; j++) v[j] = __ldg(&f4[(long)s[j] * 32 + lane]);
#pragma unroll
        for (int j = 0; j < 8; j++) nn[j] = __ldg(&g_dinv[s[j]]);
#pragma unroll
        for (int j = 0; j < 8; j++) {
            acc.x = fmaf(v[j].x, nn[j], acc.x);
            acc.y = fmaf(v[j].y, nn[j], acc.y);
            acc.z = fmaf(v[j].z, nn[j], acc.z);
            acc.w = fmaf(v[j].w, nn[j], acc.w);
        }
    }
    if (p + 4 <= pend) {
        int s[4]; float4 v[4]; float nn[4];
#pragma unroll
        for (int j = 0; j < 4; j++) s[j] = __ldg(&g_csr[p + j]);
#pragma unroll
        for (int j = 0; j < 4; j++) v[j] = __ldg(&f4[(long)s[j] * 32 + lane]);
#pragma unroll
        for (int j = 0; j < 4; j++) nn[j] = __ldg(&g_dinv[s[j]]);
#pragma unroll
        for (int j = 0; j < 4; j++) {
            acc.x = fmaf(v[j].x, nn[j], acc.x);
            acc.y = fmaf(v[j].y, nn[j], acc.y);
            acc.z = fmaf(v[j].z, nn[j], acc.z);
            acc.w = fmaf(v[j].w, nn[j], acc.w);
        }
        p += 4;
    }
    for (; p < pend; p++) {
        int s0 = __ldg(&g_csr[p]);
        float n0 = __ldg(&g_dinv[s0]);
        float4 v0 = __ldg(&f4[(long)s0 * 32 + lane]);
        acc.x = fmaf(v0.x, n0, acc.x); acc.y = fmaf(v0.y, n0, acc.y);
        acc.z = fmaf(v0.z, n0, acc.z); acc.w = fmaf(v0.w, n0, acc.w);
    }
    float4 sv = __ldg(&f4[(long)node * 32 + lane]);
    acc.x = fmaf(sv.x, dd, acc.x); acc.y = fmaf(sv.y, dd, acc.y);
    acc.z = fmaf(sv.z, dd, acc.z); acc.w = fmaf(sv.w, dd, acc.w);
    float4 bb = __ldg(&((const float4*)bias)[lane]);
    acc.x = dd * fmaxf(fmaf(acc.x, dd, bb.x), 0.f);
    acc.y = dd * fmaxf(fmaf(acc.y, dd, bb.y), 0.f);
    acc.z = dd * fmaxf(fmaf(acc.z, dd, bb.z), 0.f);
    acc.w = dd * fmaxf(fmaf(acc.w, dd, bb.w), 0.f);
    __half2 h0 = __floats2half2_rn(acc.x, acc.y);
    __half2 h1 = __floats2half2_rn(acc.z, acc.w);
    uint2 st;
    st.x = *(unsigned*)&h0;
    st.y = *(unsigned*)&h1;
    ((uint2*)out16)[(long)node * 32 + lane] = st;
}

// ------ layer-2 gather (fp16 in, fp32 out): half the L2 traffic --------------
// out = dinv_d * (sum v_s + v_d)   (inputs pre-scaled, all >= 0: no cancellation)
__global__ void gather2_k(const __half* __restrict__ feat16,
                          float* __restrict__ out, int n) {
    int node = blockIdx.x * (blockDim.x >> 5) + (threadIdx.x >> 5);
    if (node >= n) {
        cudaGridDependencySynchronize();
        return;
    }
    const int lane = threadIdx.x & 31;
    int p = g_off[node], pend = g_off[node + 1];
    float dd = g_dinv[node];
    cudaGridDependencySynchronize();               // feat16 = gather1 output
    const uint2* f2 = (const uint2*)feat16;

    float4 acc = make_float4(0.f, 0.f, 0.f, 0.f);
    for (; p + 8 <= pend; p += 8) {
        int s[8]; uint2 v[8];
#pragma unroll
        for (int j = 0; j < 8; j++) s[j] = __ldg(&g_csr[p + j]);
#pragma unroll
        for (int j = 0; j < 8; j++) v[j] = __ldg(&f2[(long)s[j] * 32 + lane]);
#pragma unroll
        for (int j = 0; j < 8; j++) {
            float2 a = __half22float2(*(__half2*)&v[j].x);
            float2 b = __half22float2(*(__half2*)&v[j].y);
            acc.x += a.x; acc.y += a.y; acc.z += b.x; acc.w += b.y;
        }
    }
    if (p + 4 <= pend) {
        int s[4]; uint2 v[4];
#pragma unroll
        for (int j = 0; j < 4; j++) s[j] = __ldg(&g_csr[p + j]);
#pragma unroll
        for (int j = 0; j < 4; j++) v[j] = __ldg(&f2[(long)s[j] * 32 + lane]);
#pragma unroll
        for (int j = 0; j < 4; j++) {
            float2 a = __half22float2(*(__half2*)&v[j].x);
            float2 b = __half22float2(*(__half2*)&v[j].y);
            acc.x += a.x; acc.y += a.y; acc.z += b.x; acc.w += b.y;
        }
        p += 4;
    }
    for (; p < pend; p++) {
        int s0 = __ldg(&g_csr[p]);
        uint2 v0 = __ldg(&f2[(long)s0 * 32 + lane]);
        float2 a = __half22float2(*(__half2*)&v0.x);
        float2 b = __half22float2(*(__half2*)&v0.y);
        acc.x += a.x; acc.y += a.y; acc.z += b.x; acc.w += b.y;
    }
    uint2 sv = __ldg(&f2[(long)node * 32 + lane]);
    float2 sa = __half22float2(*(__half2*)&sv.x);
    float2 sb = __half22float2(*(__half2*)&sv.y);
    acc.x = dd * (acc.x + sa.x);
    acc.y = dd * (acc.y + sa.y);
    acc.z = dd * (acc.z + sb.x);
    acc.w = dd * (acc.w + sb.y);
    ((float4*)out)[(long)node * 32 + lane] = acc;
}

// ------- dense transform: [rows,KIN] @ [KIN,128] ----------------------------
// EPI_MODE 0: plain store. 2: bias+relu+pool-reduce into g_sums/g_cnt.
template <int KIN, int EPI_MODE>
__global__ void gemm_k(const float* __restrict__ X, const float* __restrict__ W,
                       const float* __restrict__ bias, float* __restrict__ out,
                       const void* __restrict__ batch, int n) {
    __shared__ ulonglong2 Ws2[32 * 32];
    __shared__ ull Xs2[64 * 32];
    const int tid  = threadIdx.x;
    const int lane = tid & 31;
    const int warp = tid >> 5;
    const int rbase = blockIdx.x * 64;

    ull acc[8][2];
#pragma unroll
    for (int r = 0; r < 8; r++) { acc[r][0] = 0ull; acc[r][1] = 0ull; }

    const int KT = KIN / 32;
    for (int kt = 0; kt < KT; kt++) {
#pragma unroll
        for (int j = 0; j < 4; j++) {
            int f = tid + j * 256;
            float4 w = __ldg(&((const float4*)W)[kt * 1024 + f]);
            Ws2[f] = make_ulonglong2(pk2(w.x, w.y), pk2(w.z, w.w));
        }
        if (kt == 0) cudaGridDependencySynchronize();
#pragma unroll
        for (int j = 0; j < 2; j++) {
            int f = tid + j * 256;
            int row = f >> 3;
            int kq = f & 7;
            int gr = rbase + row;
            float4 v = make_float4(0.f, 0.f, 0.f, 0.f);
            if (gr < n)
                v = *(const float4*)(X + (long)gr * KIN + kt * 32 + kq * 4);
            int bb = row * 32 + kq * 4;
            Xs2[bb + 0] = pk2(v.x, v.x);
            Xs2[bb + 1] = pk2(v.y, v.y);
            Xs2[bb + 2] = pk2(v.z, v.z);
            Xs2[bb + 3] = pk2(v.w, v.w);
        }
        __syncthreads();
#pragma unroll
        for (int k = 0; k < 32; k++) {
            ulonglong2 w2 = Ws2[k * 32 + lane];
#pragma unroll
            for (int r = 0; r < 8; r++) {
                ull xx = Xs2[(warp * 8 + r) * 32 + k];
                ffma2(acc[r][0], xx, w2.x);
                ffma2(acc[r][1], xx, w2.y);
            }
        }
        __syncthreads();
    }
    float4 bb = make_float4(0.f, 0.f, 0.f, 0.f);
    if (EPI_MODE == 2) bb = __ldg(&((const float4*)bias)[lane]);
    int is64 = (EPI_MODE == 2) ? g_is64 : 0;
#pragma unroll
    for (int r = 0; r < 8; r++) {
        int row = rbase + warp * 8 + r;
        if (row < n) {
            float2 a = upk2(acc[r][0]);
            float2 b = upk2(acc[r][1]);
            if (EPI_MODE == 0) {
                *(float4*)(out + (long)row * HID + lane * 4) =
                    make_float4(a.x, a.y, b.x, b.y);
            } else {
                float4 o;
                o.x = fmaxf(a.x + bb.x, 0.f);
                o.y = fmaxf(a.y + bb.y, 0.f);
                o.z = fmaxf(b.x + bb.z, 0.f);
                o.w = fmaxf(b.y + bb.w, 0.f);
                int g = load_idx(batch, row, is64);
                red_add_v4(g_sums + (long)g * HID + lane * 4, o);
                if (lane == 0) atomicAdd(&g_cnt[g], 1.0f);
            }
        }
    }
}

// ------- mean + final linear (+ zero-restore g_sums/g_cnt); PDL-synced ------
__global__ void final_k(const float* __restrict__ Wlin, const float* __restrict__ blin,
                        float* __restrict__ out) {
    int g = blockIdx.x;
    int t = threadIdx.x;  // 128
    float w0 = Wlin[2 * t], w1 = Wlin[2 * t + 1];
    cudaGridDependencySynchronize();
    float c = fmaxf(g_cnt[g], 1.0f);
    float s = g_sums[g * HID + t] / c;
    g_sums[g * HID + t] = 0.f;
    if (t == 0) g_cnt[g] = 0.f;
    float p0 = s * w0;
    float p1 = s * w1;
#pragma unroll
    for (int off = 16; off; off >>= 1) {
        p0 += __shfl_down_sync(0xffffffffu, p0, off);
        p1 += __shfl_down_sync(0xffffffffu, p1, off);
    }
    __shared__ float s0[4], s1[4];
    int w = t >> 5;
    if ((t & 31) == 0) { s0[w] = p0; s1[w] = p1; }
    __syncthreads();
    if (t == 0) {
        out[g * 2 + 0] = s0[0] + s0[1] + s0[2] + s0[3] + blin[0];
        out[g * 2 + 1] = s1[0] + s1[1] + s1[2] + s1[3] + blin[1];
    }
}

// ---------------- PDL launch helper ----------------
template <typename F, typename... Args>
static void launch_pdl(F f, dim3 grid, dim3 block, cudaStream_t st, Args... args) {
    cudaLaunchConfig_t cfg = {};
    cfg.gridDim = grid;
    cfg.blockDim = block;
    cfg.dynamicSmemBytes = 0;
    cfg.stream = st;
    cudaLaunchAttribute attr[1];
    attr[0].id = cudaLaunchAttributeProgrammaticStreamSerialization;
    attr[0].val.programmaticStreamSerializationAllowed = 1;
    cfg.attrs = attr;
    cfg.numAttrs = 1;
    cudaLaunchKernelEx(&cfg, f, args...);
}

// ---------------- launcher ----------------
extern "C" void kernel_launch(void* const* d_in, const int* in_sizes, int n_in,
                              void* d_out, int out_size) {
    (void)out_size;
    const float* x     = (const float*)d_in[0];
    const void*  ei    = d_in[1];
    const void*  batch = d_in[2];
    int base = (n_in >= 10) ? 4 : 3;
    const float* W1   = (const float*)d_in[base + 0];
    const float* b1   = (const float*)d_in[base + 1];
    const float* W2   = (const float*)d_in[base + 2];
    const float* b2   = (const float*)d_in[base + 3];
    const float* Wlin = (const float*)d_in[base + 4];
    const float* blin = (const float*)d_in[base + 5];

    const int N = in_sizes[0] / 96;
    const int E = in_sizes[1] / 2;
    const int NBLK = (N + 1023) >> 10;  // <= 49
    float* out = (float*)d_out;

    static cudaStream_t s1 = 0;
    static cudaEvent_t evF, evJ;
    if (!s1) {
        cudaStreamCreateWithFlags(&s1, cudaStreamNonBlocking);
        cudaEventCreateWithFlags(&evF, cudaEventDisableTiming);
        cudaEventCreateWithFlags(&evJ, cudaEventDisableTiming);
    }

    void *p_a16, *p_h;
    cudaGetSymbolAddress(&p_a16, g_a16);
    cudaGetSymbolAddress(&p_h, g_h);

    // fork: h1 = x @ W1 on s1 (independent of graph prep)
    cudaEventRecord(evF, 0);
    cudaStreamWaitEvent(s1, evF, 0);
    gemm_k<96, 0><<<(N + 63) / 64, 256, 0, s1>>>(x, W1, nullptr,
                                                 (float*)p_h, nullptr, N);
    cudaEventRecord(evJ, s1);

    // prep chain on stream 0 (no memsets; PDL-overlapped boundaries)
    rank_k<<<(E + 2047) / 2048, 256>>>(ei, E);
    launch_pdl(scan_k, dim3(NBLK), dim3(1024), (cudaStream_t)0, N, NBLK);
    launch_pdl(fill2_k, dim3((E + 2047) / 2048), dim3(256), (cudaStream_t)0,
               ei, E);

    // layer-1 gather (fp32 -> fp16 act1'); gemm96 event edge is a full barrier
    cudaStreamWaitEvent(0, evJ, 0);
    launch_pdl(gather1_k, dim3((N + 7) / 8), dim3(256), (cudaStream_t)0,
               (const float*)p_h, b1, (__half*)p_a16, N);

    // layer 2: fp16 aggregate of act1' -> g_h (fp32), then gemm + pool
    launch_pdl(gather2_k, dim3((N + 7) / 8), dim3(256), (cudaStream_t)0,
               (const __half*)p_a16, (float*)p_h, N);
    launch_pdl(gemm_k<128, 2>, dim3((N + 63) / 64), dim3(256), (cudaStream_t)0,
               (const float*)p_h, W2, b2, (float*)nullptr, (const void*)batch, N);

    launch_pdl(final_k, dim3(N_GRAPHS), dim3(HID), (cudaStream_t)0,
               Wlin, blin, out);
}

// round 17
// speedup vs baseline: 1.2065x; 1.0032x over previous
#include <cuda_runtime.h>
#include <cuda_fp16.h>
#include <math.h>

#define N_NODES_MAX 50000
#define E_MAX 800000
#define N_GRAPHS 512
#define HID 128

typedef unsigned long long ull;

// ------------- scratch (zero at load; zero-invariants maintained) ----------
__device__ __half g_h16[(size_t)N_NODES_MAX * HID]; // h1 (fp16), later agg2 (fp16)
__device__ __half g_a16[(size_t)N_NODES_MAX * HID]; // act1' (fp16, >=0)
__device__ int    g_degi[N_NODES_MAX];              // INVARIANT: zero between calls
__device__ int    g_off[N_NODES_MAX + 1];
__device__ float  g_dinv[N_NODES_MAX];              // 1/sqrt(deg+1)
__device__ int    g_rank[E_MAX];                    // per-edge rank within dst
__device__ int    g_csr[E_MAX];                     // src ids grouped by dst
__device__ int    g_bsum[64];                       // zeroed by rank_k block 0
__device__ float  g_sums[N_GRAPHS * HID];           // INVARIANT: zero between calls
__device__ float  g_cnt[N_GRAPHS];                  // INVARIANT: zero between calls
__device__ int    g_is64;

// ---------------- packed f32x2 helpers ----------------
__device__ __forceinline__ ull pk2(float a, float b) {
    ull r;
    asm("mov.b64 %0, {%1, %2};" : "=l"(r) : "f"(a), "f"(b));
    return r;
}
__device__ __forceinline__ float2 upk2(ull v) {
    float2 f;
    asm("mov.b64 {%0, %1}, %2;" : "=f"(f.x), "=f"(f.y) : "l"(v));
    return f;
}
__device__ __forceinline__ void ffma2(ull& d, ull a, ull b) {
    asm("fma.rn.f32x2 %0, %1, %2, %3;" : "=l"(d) : "l"(a), "l"(b), "l"(d));
}
__device__ __forceinline__ int load_idx(const void* p, long i, int is64) {
    if (is64) return (int)((const long long*)p)[i];
    return ((const int*)p)[i];
}
__device__ __forceinline__ void red_add_v4(float* addr, float4 v) {
    size_t ga = __cvta_generic_to_global(addr);
    asm volatile("red.global.add.v4.f32 [%0], {%1, %2, %3, %4};"
                 :: "l"(ga), "f"(v.x), "f"(v.y), "f"(v.z), "f"(v.w) : "memory");
}
__device__ __forceinline__ uint2 f4_to_h4(float4 a) {
    __half2 h0 = __floats2half2_rn(a.x, a.y);
    __half2 h1 = __floats2half2_rn(a.z, a.w);
    uint2 r;
    r.x = *(unsigned*)&h0;
    r.y = *(unsigned*)&h1;
    return r;
}
__device__ __forceinline__ float4 h4_to_f4(uint2 v) {
    float2 a = __half22float2(*(__half2*)&v.x);
    float2 b = __half22float2(*(__half2*)&v.y);
    return make_float4(a.x, a.y, b.x, b.y);
}

// ------- rank pass: degree histogram + per-edge rank + dtype detect ---------
__global__ void rank_k(const void* __restrict__ ei, int E) {
    __shared__ int s64;
    if (threadIdx.x == 0) {
        const ull* e = (const ull*)ei;
        int f = 1;
#pragma unroll
        for (int i = 0; i < 16; i++)
            if (e[i] >> 32) f = 0;
        s64 = f;
        if (blockIdx.x == 0) g_is64 = f;
    }
    if (blockIdx.x == 0 && threadIdx.x < 64) g_bsum[threadIdx.x] = 0;
    __syncthreads();
    int is64 = s64;
    long base = ((long)blockIdx.x * blockDim.x + threadIdx.x) * 8;
#pragma unroll
    for (int j = 0; j < 8; j++) {
        long e = base + j;
        if (e < E) {
            int d = load_idx(ei, (long)E + e, is64);
            g_rank[e] = atomicAdd(&g_degi[d], 1);
        }
    }
}

// ------- single-pass scan with decoupled lookback; restores g_degi=0 --------
__global__ void scan_k(int n, int nblk) {
    cudaGridDependencySynchronize();
    __shared__ int wsum[32];
    __shared__ int s_carry;
    const int tid = threadIdx.x, lane = tid & 31, w = tid >> 5;
    const int b = blockIdx.x;
    int i = b * 1024 + tid;
    int v = (i < n) ? g_degi[i] : 0;
    if (i < n) g_degi[i] = 0;
    int x = v;
#pragma unroll
    for (int o = 1; o < 32; o <<= 1) {
        int y = __shfl_up_sync(~0u, x, o);
        if (lane >= o) x += y;
    }
    if (lane == 31) wsum[w] = x;
    __syncthreads();
    if (w == 0) {
        int s = wsum[lane];
#pragma unroll
        for (int o = 1; o < 32; o <<= 1) {
            int y = __shfl_up_sync(~0u, s, o);
            if (lane >= o) s += y;
        }
        wsum[lane] = s;
    }
    __syncthreads();
    int pre = (w > 0) ? wsum[w - 1] : 0;
    int incl = pre + x;
    int btotal = wsum[31];
    if (tid == 0) atomicExch(&g_bsum[b], btotal + 1);
    if (w == 0) {
        int sum = 0;
        for (int base = 0; base < b; base += 32) {
            int idx = base + lane;
            int val = 0;
            if (idx < b) {
                do { val = atomicAdd(&g_bsum[idx], 0); } while (val == 0);
                sum += val - 1;
            }
        }
#pragma unroll
        for (int o = 16; o; o >>= 1)
            sum += __shfl_down_sync(~0u, sum, o);
        if (lane == 0) s_carry = sum;
    }
    __syncthreads();
    int bpre = s_carry;
    if (i < n) {
        g_off[i] = bpre + incl - v;
        g_dinv[i] = rsqrtf((float)v + 1.0f);
    }
    if (b == nblk - 1 && tid == 1023) g_off[n] = bpre + incl;
}

// ---------- CSR fill: NO atomics. PDL: pre-load edge list before gridsync ---
__global__ void fill2_k(const void* __restrict__ ei, int E) {
    __shared__ int s64;
    if (threadIdx.x == 0) {
        const ull* e = (const ull*)ei;
        int f = 1;
#pragma unroll
        for (int i = 0; i < 16; i++)
            if (e[i] >> 32) f = 0;
        s64 = f;
    }
    __syncthreads();
    int is64 = s64;
    long base = ((long)blockIdx.x * blockDim.x + threadIdx.x) * 8;
    int s[8], d[8];
#pragma unroll
    for (int j = 0; j < 8; j++) {
        long e = base + j;
        if (e < E) {
            s[j] = load_idx(ei, e, is64);
            d[j] = load_idx(ei, (long)E + e, is64);
        } else d[j] = -1;
    }
    cudaGridDependencySynchronize();
#pragma unroll
    for (int j = 0; j < 8; j++) {
        long e = base + j;
        if (d[j] >= 0) g_csr[g_off[d[j]] + g_rank[e]] = s[j];
    }
}

// ------ layer-1 gather (fp16 in, fp16 out): warp per dst node, 8-edge ILP ---
// out16 = half( dinv_d * relu(dinv_d*(sum dinv_s*v_s + dinv_d*v_d) + bias) )
__global__ void gather1_k(const __half* __restrict__ feat16,
                          const float* __restrict__ bias,
                          __half* __restrict__ out16, int n) {
    int node = blockIdx.x * (blockDim.x >> 5) + (threadIdx.x >> 5);
    if (node >= n) {
        cudaGridDependencySynchronize();
        return;
    }
    const int lane = threadIdx.x & 31;
    int p = g_off[node], pend = g_off[node + 1];   // ancient data: pre-sync safe
    float dd = g_dinv[node];
    cudaGridDependencySynchronize();               // feat16 = gemm96 output
    const uint2* f2 = (const uint2*)feat16;

    float4 acc = make_float4(0.f, 0.f, 0.f, 0.f);
    for (; p + 8 <= pend; p += 8) {
        int s[8]; uint2 v[8]; float nn[8];
#pragma unroll
        for (int j = 0; j < 8; j++) s[j] = __ldg(&g_csr[p + j]);
#pragma unroll
        for (int j = 0; j < 8; j++) v[j] = __ldg(&f2[(long)s[j] * 32 + lane]);
#pragma unroll
        for (int j = 0; j < 8; j++) nn[j] = __ldg(&g_dinv[s[j]]);
#pragma unroll
        for (int j = 0; j < 8; j++) {
            float4 f = h4_to_f4(v[j]);
            acc.x = fmaf(f.x, nn[j], acc.x);
            acc.y = fmaf(f.y, nn[j], acc.y);
            acc.z = fmaf(f.z, nn[j], acc.z);
            acc.w = fmaf(f.w, nn[j], acc.w);
        }
    }
    if (p + 4 <= pend) {
        int s[4]; uint2 v[4]; float nn[4];
#pragma unroll
        for (int j = 0; j < 4; j++) s[j] = __ldg(&g_csr[p + j]);
#pragma unroll
        for (int j = 0; j < 4; j++) v[j] = __ldg(&f2[(long)s[j] * 32 + lane]);
#pragma unroll
        for (int j = 0; j < 4; j++) nn[j] = __ldg(&g_dinv[s[j]]);
#pragma unroll
        for (int j = 0; j < 4; j++) {
            float4 f = h4_to_f4(v[j]);
            acc.x = fmaf(f.x, nn[j], acc.x);
            acc.y = fmaf(f.y, nn[j], acc.y);
            acc.z = fmaf(f.z, nn[j], acc.z);
            acc.w = fmaf(f.w, nn[j], acc.w);
        }
        p += 4;
    }
    for (; p < pend; p++) {
        int s0 = __ldg(&g_csr[p]);
        float n0 = __ldg(&g_dinv[s0]);
        float4 f = h4_to_f4(__ldg(&f2[(long)s0 * 32 + lane]));
        acc.x = fmaf(f.x, n0, acc.x); acc.y = fmaf(f.y, n0, acc.y);
        acc.z = fmaf(f.z, n0, acc.z); acc.w = fmaf(f.w, n0, acc.w);
    }
    float4 sv = h4_to_f4(__ldg(&f2[(long)node * 32 + lane]));
    acc.x = fmaf(sv.x, dd, acc.x); acc.y = fmaf(sv.y, dd, acc.y);
    acc.z = fmaf(sv.z, dd, acc.z); acc.w = fmaf(sv.w, dd, acc.w);
    float4 bb = __ldg(&((const float4*)bias)[lane]);
    acc.x = dd * fmaxf(fmaf(acc.x, dd, bb.x), 0.f);
    acc.y = dd * fmaxf(fmaf(acc.y, dd, bb.y), 0.f);
    acc.z = dd * fmaxf(fmaf(acc.z, dd, bb.z), 0.f);
    acc.w = dd * fmaxf(fmaf(acc.w, dd, bb.w), 0.f);
    ((uint2*)out16)[(long)node * 32 + lane] = f4_to_h4(acc);
}

// ------ layer-2 gather (fp16 in, fp16 out): all terms >= 0 ------------------
// out16 = half( dinv_d * (sum v_s + v_d) )
__global__ void gather2_k(const __half* __restrict__ feat16,
                          __half* __restrict__ out16, int n) {
    int node = blockIdx.x * (blockDim.x >> 5) + (threadIdx.x >> 5);
    if (node >= n) {
        cudaGridDependencySynchronize();
        return;
    }
    const int lane = threadIdx.x & 31;
    int p = g_off[node], pend = g_off[node + 1];
    float dd = g_dinv[node];
    cudaGridDependencySynchronize();               // feat16 = gather1 output
    const uint2* f2 = (const uint2*)feat16;

    float4 acc = make_float4(0.f, 0.f, 0.f, 0.f);
    for (; p + 8 <= pend; p += 8) {
        int s[8]; uint2 v[8];
#pragma unroll
        for (int j = 0; j < 8; j++) s[j] = __ldg(&g_csr[p + j]);
#pragma unroll
        for (int j = 0; j < 8; j++) v[j] = __ldg(&f2[(long)s[j] * 32 + lane]);
#pragma unroll
        for (int j = 0; j < 8; j++) {
            float4 f = h4_to_f4(v[j]);
            acc.x += f.x; acc.y += f.y; acc.z += f.z; acc.w += f.w;
        }
    }
    if (p + 4 <= pend) {
        int s[4]; uint2 v[4];
#pragma unroll
        for (int j = 0; j < 4; j++) s[j] = __ldg(&g_csr[p + j]);
#pragma unroll
        for (int j = 0; j < 4; j++) v[j] = __ldg(&f2[(long)s[j] * 32 + lane]);
#pragma unroll
        for (int j = 0; j < 4; j++) {
            float4 f = h4_to_f4(v[j]);
            acc.x += f.x; acc.y += f.y; acc.z += f.z; acc.w += f.w;
        }
        p += 4;
    }
    for (; p < pend; p++) {
        int s0 = __ldg(&g_csr[p]);
        float4 f = h4_to_f4(__ldg(&f2[(long)s0 * 32 + lane]));
        acc.x += f.x; acc.y += f.y; acc.z += f.z; acc.w += f.w;
    }
    float4 sv = h4_to_f4(__ldg(&f2[(long)node * 32 + lane]));
    acc.x = dd * (acc.x + sv.x);
    acc.y = dd * (acc.y + sv.y);
    acc.z = dd * (acc.z + sv.z);
    acc.w = dd * (acc.w + sv.w);
    ((uint2*)out16)[(long)node * 32 + lane] = f4_to_h4(acc);
}

// ------- layer-1 gemm: h1 = X @ W1 (fp32 in, fp16 out) ----------------------
__global__ void gemm96h_k(const float* __restrict__ X, const float* __restrict__ W,
                          __half* __restrict__ out16, int n) {
    __shared__ ulonglong2 Ws2[32 * 32];
    __shared__ ull Xs2[64 * 32];
    const int tid  = threadIdx.x;
    const int lane = tid & 31;
    const int warp = tid >> 5;
    const int rbase = blockIdx.x * 64;

    ull acc[8][2];
#pragma unroll
    for (int r = 0; r < 8; r++) { acc[r][0] = 0ull; acc[r][1] = 0ull; }

    for (int kt = 0; kt < 3; kt++) {
#pragma unroll
        for (int j = 0; j < 4; j++) {
            int f = tid + j * 256;
            float4 w = __ldg(&((const float4*)W)[kt * 1024 + f]);
            Ws2[f] = make_ulonglong2(pk2(w.x, w.y), pk2(w.z, w.w));
        }
#pragma unroll
        for (int j = 0; j < 2; j++) {
            int f = tid + j * 256;
            int row = f >> 3;
            int kq = f & 7;
            int gr = rbase + row;
            float4 v = make_float4(0.f, 0.f, 0.f, 0.f);
            if (gr < n)
                v = *(const float4*)(X + (long)gr * 96 + kt * 32 + kq * 4);
            int bb = row * 32 + kq * 4;
            Xs2[bb + 0] = pk2(v.x, v.x);
            Xs2[bb + 1] = pk2(v.y, v.y);
            Xs2[bb + 2] = pk2(v.z, v.z);
            Xs2[bb + 3] = pk2(v.w, v.w);
        }
        __syncthreads();
#pragma unroll
        for (int k = 0; k < 32; k++) {
            ulonglong2 w2 = Ws2[k * 32 + lane];
#pragma unroll
            for (int r = 0; r < 8; r++) {
                ull xx = Xs2[(warp * 8 + r) * 32 + k];
                ffma2(acc[r][0], xx, w2.x);
                ffma2(acc[r][1], xx, w2.y);
            }
        }
        __syncthreads();
    }
#pragma unroll
    for (int r = 0; r < 8; r++) {
        int row = rbase + warp * 8 + r;
        if (row < n) {
            float2 a = upk2(acc[r][0]);
            float2 b = upk2(acc[r][1]);
            ((uint2*)out16)[(long)row * 32 + lane] =
                f4_to_h4(make_float4(a.x, a.y, b.x, b.y));
        }
    }
}

// ------- layer-2 gemm (fp16 in) + bias + relu + pool -------------------------
__global__ void gemm128h_k(const __half* __restrict__ X16,
                           const float* __restrict__ W,
                           const float* __restrict__ bias,
                           const void* __restrict__ batch, int n) {
    __shared__ ulonglong2 Ws2[32 * 32];
    __shared__ ull Xs2[64 * 32];
    const int tid  = threadIdx.x;
    const int lane = tid & 31;
    const int warp = tid >> 5;
    const int rbase = blockIdx.x * 64;

    ull acc[8][2];
#pragma unroll
    for (int r = 0; r < 8; r++) { acc[r][0] = 0ull; acc[r][1] = 0ull; }

    for (int kt = 0; kt < 4; kt++) {
#pragma unroll
        for (int j = 0; j < 4; j++) {
            int f = tid + j * 256;
            float4 w = __ldg(&((const float4*)W)[kt * 1024 + f]);
            Ws2[f] = make_ulonglong2(pk2(w.x, w.y), pk2(w.z, w.w));
        }
        if (kt == 0) cudaGridDependencySynchronize();
#pragma unroll
        for (int j = 0; j < 2; j++) {
            int f = tid + j * 256;
            int row = f >> 3;
            int kq = f & 7;
            int gr = rbase + row;
            uint2 v = make_uint2(0u, 0u);
            if (gr < n)
                v = *(const uint2*)(X16 + (long)gr * HID + kt * 32 + kq * 4);
            float4 fv = h4_to_f4(v);
            int bb = row * 32 + kq * 4;
            Xs2[bb + 0] = pk2(fv.x, fv.x);
            Xs2[bb + 1] = pk2(fv.y, fv.y);
            Xs2[bb + 2] = pk2(fv.z, fv.z);
            Xs2[bb + 3] = pk2(fv.w, fv.w);
        }
        __syncthreads();
#pragma unroll
        for (int k = 0; k < 32; k++) {
            ulonglong2 w2 = Ws2[k * 32 + lane];
#pragma unroll
            for (int r = 0; r < 8; r++) {
                ull xx = Xs2[(warp * 8 + r) * 32 + k];
                ffma2(acc[r][0], xx, w2.x);
                ffma2(acc[r][1], xx, w2.y);
            }
        }
        __syncthreads();
    }
    float4 bb = __ldg(&((const float4*)bias)[lane]);
    int is64 = g_is64;
#pragma unroll
    for (int r = 0; r < 8; r++) {
        int row = rbase + warp * 8 + r;
        if (row < n) {
            float2 a = upk2(acc[r][0]);
            float2 b = upk2(acc[r][1]);
            float4 o;
            o.x = fmaxf(a.x + bb.x, 0.f);
            o.y = fmaxf(a.y + bb.y, 0.f);
            o.z = fmaxf(b.x + bb.z, 0.f);
            o.w = fmaxf(b.y + bb.w, 0.f);
            int g = load_idx(batch, row, is64);
            red_add_v4(g_sums + (long)g * HID + lane * 4, o);
            if (lane == 0) atomicAdd(&g_cnt[g], 1.0f);
        }
    }
}

// ------- mean + final linear (+ zero-restore g_sums/g_cnt); PDL-synced ------
__global__ void final_k(const float* __restrict__ Wlin, const float* __restrict__ blin,
                        float* __restrict__ out) {
    int g = blockIdx.x;
    int t = threadIdx.x;  // 128
    float w0 = Wlin[2 * t], w1 = Wlin[2 * t + 1];
    cudaGridDependencySynchronize();
    float c = fmaxf(g_cnt[g], 1.0f);
    float s = g_sums[g * HID + t] / c;
    g_sums[g * HID + t] = 0.f;
    if (t == 0) g_cnt[g] = 0.f;
    float p0 = s * w0;
    float p1 = s * w1;
#pragma unroll
    for (int off = 16; off; off >>= 1) {
        p0 += __shfl_down_sync(0xffffffffu, p0, off);
        p1 += __shfl_down_sync(0xffffffffu, p1, off);
    }
    __shared__ float s0[4], s1[4];
    int w = t >> 5;
    if ((t & 31) == 0) { s0[w] = p0; s1[w] = p1; }
    __syncthreads();
    if (t == 0) {
        out[g * 2 + 0] = s0[0] + s0[1] + s0[2] + s0[3] + blin[0];
        out[g * 2 + 1] = s1[0] + s1[1] + s1[2] + s1[3] + blin[1];
    }
}

// ---------------- PDL launch helper ----------------
template <typename F, typename... Args>
static void launch_pdl(F f, dim3 grid, dim3 block, cudaStream_t st, Args... args) {
    cudaLaunchConfig_t cfg = {};
    cfg.gridDim = grid;
    cfg.blockDim = block;
    cfg.dynamicSmemBytes = 0;
    cfg.stream = st;
    cudaLaunchAttribute attr[1];
    attr[0].id = cudaLaunchAttributeProgrammaticStreamSerialization;
    attr[0].val.programmaticStreamSerializationAllowed = 1;
    cfg.attrs = attr;
    cfg.numAttrs = 1;
    cudaLaunchKernelEx(&cfg, f, args...);
}

// ---------------- launcher ----------------
extern "C" void kernel_launch(void* const* d_in, const int* in_sizes, int n_in,
                              void* d_out, int out_size) {
    (void)out_size;
    const float* x     = (const float*)d_in[0];
    const void*  ei    = d_in[1];
    const void*  batch = d_in[2];
    int base = (n_in >= 10) ? 4 : 3;
    const float* W1   = (const float*)d_in[base + 0];
    const float* b1   = (const float*)d_in[base + 1];
    const float* W2   = (const float*)d_in[base + 2];
    const float* b2   = (const float*)d_in[base + 3];
    const float* Wlin = (const float*)d_in[base + 4];
    const float* blin = (const float*)d_in[base + 5];

    const int N = in_sizes[0] / 96;
    const int E = in_sizes[1] / 2;
    const int NBLK = (N + 1023) >> 10;  // <= 49
    float* out = (float*)d_out;

    static cudaStream_t s1 = 0;
    static cudaEvent_t evF, evJ;
    if (!s1) {
        cudaStreamCreateWithFlags(&s1, cudaStreamNonBlocking);
        cudaEventCreateWithFlags(&evF, cudaEventDisableTiming);
        cudaEventCreateWithFlags(&evJ, cudaEventDisableTiming);
    }

    void *p_a16, *p_h16;
    cudaGetSymbolAddress(&p_a16, g_a16);
    cudaGetSymbolAddress(&p_h16, g_h16);

    // fork: h1 = x @ W1 (fp16 out) on s1 (independent of graph prep)
    cudaEventRecord(evF, 0);
    cudaStreamWaitEvent(s1, evF, 0);
    gemm96h_k<<<(N + 63) / 64, 256, 0, s1>>>(x, W1, (__half*)p_h16, N);
    cudaEventRecord(evJ, s1);

    // prep chain on stream 0 (no memsets; PDL-overlapped boundaries)
    rank_k<<<(E + 2047) / 2048, 256>>>(ei, E);
    launch_pdl(scan_k, dim3(NBLK), dim3(1024), (cudaStream_t)0, N, NBLK);
    launch_pdl(fill2_k, dim3((E + 2047) / 2048), dim3(256), (cudaStream_t)0,
               ei, E);

    // layer-1 gather (fp16 -> fp16 act1'); gemm96 event edge is a full barrier
    cudaStreamWaitEvent(0, evJ, 0);
    launch_pdl(gather1_k, dim3((N + 7) / 8), dim3(256), (cudaStream_t)0,
               (const __half*)p_h16, b1, (__half*)p_a16, N);

    // layer 2: fp16 aggregate of act1' -> g_h16 (reuse; h1 is dead), then gemm+pool
    launch_pdl(gather2_k, dim3((N + 7) / 8), dim3(256), (cudaStream_t)0,
               (const __half*)p_a16, (__half*)p_h16, N);
    launch_pdl(gemm128h_k, dim3((N + 63) / 64), dim3(256), (cudaStream_t)0,
               (const __half*)p_h16, W2, b2, (const void*)batch, N);

    launch_pdl(final_k, dim3(N_GRAPHS), dim3(HID), (cudaStream_t)0,
               Wlin, blin, out);
}